// round 4
// baseline (speedup 1.0000x reference)
#include <cuda_runtime.h>
#include <cuda_bf16.h>
#include <math.h>
#include <stdint.h>

// ---------------- problem constants ----------------
#define Bsz  8
#define Lseq 2049
#define Dmod 256
#define DI   512
#define DS   16
#define DRK  16
#define LB   1025    // per-branch input length (mid = L//2+1 = 1025)
#define LC   1028    // conv output length: 1025 + 2*3 - 4 + 1
#define Stok 64
#define NXP  48      // dt_rank + 2*d_state
#define LCP  1040    // LC padded to 16 for tensor K

// ---------------- fp32 scratch ----------------
__device__ float g_xi[Bsz*Lseq*DI];
__device__ float g_uf[Bsz*LC*DI];
__device__ float g_ub[Bsz*LC*DI];
__device__ float g_dbcf[Bsz*LC*NXP];
__device__ float g_dbcb[Bsz*LC*NXP];
__device__ float g_deltaf[Bsz*LC*DI];
__device__ float g_deltab[Bsz*LC*DI];
__device__ float g_yf[Bsz*LC*DI];
__device__ float g_yb[Bsz*LC*DI];
__device__ float g_y[Bsz*LC*DI];
__device__ float g_mf[Bsz*LC];
__device__ float g_mb[Bsz*LC];
__device__ float g_mc[Bsz*LC];
__device__ float g_dist[Bsz*LC];
__device__ float g_zp[Bsz*Stok*DI];
__device__ float g_scores[Bsz*LC*Stok];

// ---------------- bf16 hi/lo split planes ----------------
__device__ __nv_bfloat16 g_xh[Bsz*Lseq*Dmod],   g_xl[Bsz*Lseq*Dmod];
__device__ __nv_bfloat16 g_Winx_h[DI*Dmod],     g_Winx_l[DI*Dmod];
__device__ __nv_bfloat16 g_Winz_h[DI*Dmod],     g_Winz_l[DI*Dmod];
__device__ __nv_bfloat16 g_xph[Bsz*Stok*Dmod],  g_xpl[Bsz*Stok*Dmod];
__device__ __nv_bfloat16 g_ufh[Bsz*LC*DI],      g_ufl[Bsz*LC*DI];
__device__ __nv_bfloat16 g_ubh[Bsz*LC*DI],      g_ubl[Bsz*LC*DI];
__device__ __nv_bfloat16 g_Wxpf_h[128*DI],      g_Wxpf_l[128*DI];
__device__ __nv_bfloat16 g_Wxpb_h[128*DI],      g_Wxpb_l[128*DI];
__device__ __nv_bfloat16 g_dbcfh[Bsz*LC*NXP],   g_dbcfl[Bsz*LC*NXP];
__device__ __nv_bfloat16 g_dbcbh[Bsz*LC*NXP],   g_dbcbl[Bsz*LC*NXP];
__device__ __nv_bfloat16 g_Wdtf_h[DI*DRK],      g_Wdtf_l[DI*DRK];
__device__ __nv_bfloat16 g_Wdtb_h[DI*DRK],      g_Wdtb_l[DI*DRK];
__device__ __nv_bfloat16 g_ycat_h[Bsz*LC*2*DI], g_ycat_l[Bsz*LC*2*DI];
__device__ __nv_bfloat16 g_Wpro_h[DI*2*DI],     g_Wpro_l[DI*2*DI];
__device__ __nv_bfloat16 g_yh[Bsz*LC*DI+16*DI], g_yl[Bsz*LC*DI+16*DI]; // slack rows stay 0
__device__ __nv_bfloat16 g_wA_h[128*DI],        g_wA_l[128*DI];
__device__ __nv_bfloat16 g_akh[Bsz*Stok*LCP],   g_akl[Bsz*Stok*LCP];
__device__ __nv_bfloat16 g_tyh[Bsz*Stok*DI],    g_tyl[Bsz*Stok*DI];
__device__ __nv_bfloat16 g_wV_h[DI*DI],         g_wV_l[DI*DI];
__device__ __nv_bfloat16 g_Th[Bsz*Stok*DI],     g_Tl[Bsz*Stok*DI];
__device__ __nv_bfloat16 g_Wout_h[Dmod*DI],     g_Wout_l[Dmod*DI];

// ---------------- split helpers ----------------
__device__ __forceinline__ void splitv(float v, __nv_bfloat16& h, __nv_bfloat16& l) {
    h = __float2bfloat16(v);
    l = __float2bfloat16(v - __bfloat162float(h));
}

__global__ void split_kernel(const float* __restrict__ src,
                             __nv_bfloat16* __restrict__ hi, __nv_bfloat16* __restrict__ lo, int n)
{
    int i = blockIdx.x * 256 + threadIdx.x;
    if (i < n) { __nv_bfloat16 h, l; splitv(src[i], h, l); hi[i] = h; lo[i] = l; }
}

// pad rows beyond rows_src with zeros
__global__ void split_pad_kernel(const float* __restrict__ src,
                                 __nv_bfloat16* __restrict__ hi, __nv_bfloat16* __restrict__ lo,
                                 int rows_src, int cols, int rows_tot)
{
    int i = blockIdx.x * 256 + threadIdx.x;
    if (i < rows_tot * cols) {
        float v = (i < rows_src * cols) ? src[i] : 0.f;
        __nv_bfloat16 h, l; splitv(v, h, l); hi[i] = h; lo[i] = l;
    }
}

// =====================================================================
// Tensor-core GEMM on pre-split bf16 hi/lo planes.
// C = A(M,K) * op(B) with 3-way split MMAs (hh + hl + lh), fp32 accum.
// TB=1: B planes are (N,K) row-major. TB=0: B planes are (K,N) row-major.
// N (buffer domain) % 128 == 0; writes guarded by Nout. K % 16 == 0.
// lda/ldb % 8 == 0. Optional: bias, act(1=silu,2=softplus), emul gate,
// fp32 C and/or bf16 split outputs Ch/Cl. z-batched by strides.
// =====================================================================
#define SAS 24

__device__ __forceinline__ uint32_t s2u(const void* p) {
    return (uint32_t)__cvta_generic_to_shared(p);
}
__device__ __forceinline__ void ldsm4(uint32_t r[4], uint32_t addr) {
    asm volatile("ldmatrix.sync.aligned.m8n8.x4.shared.b16 {%0,%1,%2,%3}, [%4];"
                 : "=r"(r[0]), "=r"(r[1]), "=r"(r[2]), "=r"(r[3]) : "r"(addr));
}
__device__ __forceinline__ void mma16816(float c[4], const uint32_t a[4],
                                         uint32_t b0, uint32_t b1) {
    asm volatile(
        "mma.sync.aligned.m16n8k16.row.col.f32.bf16.bf16.f32 "
        "{%0,%1,%2,%3},{%4,%5,%6,%7},{%8,%9},{%0,%1,%2,%3};"
        : "+f"(c[0]), "+f"(c[1]), "+f"(c[2]), "+f"(c[3])
        : "r"(a[0]), "r"(a[1]), "r"(a[2]), "r"(a[3]), "r"(b0), "r"(b1));
}

template<int TB>
__global__ __launch_bounds__(256, 2)
void hgemm2(const __nv_bfloat16* __restrict__ Ah, const __nv_bfloat16* __restrict__ Al,
            const __nv_bfloat16* __restrict__ Bh, const __nv_bfloat16* __restrict__ Bl,
            const float* __restrict__ bias, const float* __restrict__ emul,
            float* __restrict__ C,
            __nv_bfloat16* __restrict__ Ch, __nv_bfloat16* __restrict__ Cl,
            int M, int N, int K, int lda, int ldb, int ldc, int Nout, int act,
            long long sA, long long sB, long long sC)
{
    __shared__ __align__(16) __nv_bfloat16 As_hi[128][SAS];
    __shared__ __align__(16) __nv_bfloat16 As_lo[128][SAS];
    __shared__ __align__(16) __nv_bfloat16 Bs_hi[128][SAS];
    __shared__ __align__(16) __nv_bfloat16 Bs_lo[128][SAS];

    int bz = blockIdx.z;
    Ah += bz * sA; Al += bz * sA;
    Bh += bz * sB; Bl += bz * sB;

    int tid  = threadIdx.x;
    int lane = tid & 31;
    int wid  = tid >> 5;
    int wm0  = (wid >> 2) * 64;
    int wn0  = (wid & 3) * 32;
    int row0 = blockIdx.y * 128;
    int col0 = blockIdx.x * 128;

    int lr = lane & 15;
    int lc = (lane >> 4) * 8;

    // tile-load coords
    int ar = tid >> 1;            // 0..127
    int ah8 = (tid & 1) * 8;      // 0 or 8
    int bkk = tid >> 4;           // TB=0: 0..15
    int bnc = (tid & 15) * 8;     // TB=0: 0..120

    float acc[4][4][4];
    #pragma unroll
    for (int i = 0; i < 4; i++)
        #pragma unroll
        for (int j = 0; j < 4; j++)
            #pragma unroll
            for (int q = 0; q < 4; q++) acc[i][j][q] = 0.f;

    for (int k0 = 0; k0 < K; k0 += 16) {
        // ---- A tile ----
        {
            int gm = row0 + ar;
            uint4 vh = make_uint4(0,0,0,0), vl = make_uint4(0,0,0,0);
            if (gm < M) {
                vh = *(const uint4*)(Ah + (long long)gm * lda + k0 + ah8);
                vl = *(const uint4*)(Al + (long long)gm * lda + k0 + ah8);
            }
            *(uint4*)&As_hi[ar][ah8] = vh;
            *(uint4*)&As_lo[ar][ah8] = vl;
        }
        // ---- B tile ----
        if (TB == 1) {
            int gn = col0 + ar;   // buffers padded to N rows
            uint4 vh = *(const uint4*)(Bh + (long long)gn * ldb + k0 + ah8);
            uint4 vl = *(const uint4*)(Bl + (long long)gn * ldb + k0 + ah8);
            *(uint4*)&Bs_hi[ar][ah8] = vh;
            *(uint4*)&Bs_lo[ar][ah8] = vl;
        } else {
            uint4 vh = *(const uint4*)(Bh + (long long)(k0 + bkk) * ldb + col0 + bnc);
            uint4 vl = *(const uint4*)(Bl + (long long)(k0 + bkk) * ldb + col0 + bnc);
            __nv_bfloat16 th[8], tl[8];
            *(uint4*)th = vh; *(uint4*)tl = vl;
            #pragma unroll
            for (int j = 0; j < 8; j++) {
                Bs_hi[bnc + j][bkk] = th[j];
                Bs_lo[bnc + j][bkk] = tl[j];
            }
        }
        __syncthreads();

        uint32_t bh[2][4], bl[2][4];
        #pragma unroll
        for (int ng = 0; ng < 2; ng++) {
            ldsm4(bh[ng], s2u(&Bs_hi[wn0 + ng * 16 + lr][lc]));
            ldsm4(bl[ng], s2u(&Bs_lo[wn0 + ng * 16 + lr][lc]));
        }
        #pragma unroll
        for (int mt = 0; mt < 4; mt++) {
            uint32_t a_h[4], a_l[4];
            ldsm4(a_h, s2u(&As_hi[wm0 + mt * 16 + lr][lc]));
            ldsm4(a_l, s2u(&As_lo[wm0 + mt * 16 + lr][lc]));
            #pragma unroll
            for (int nt = 0; nt < 4; nt++) {
                int ng = nt >> 1, sl = nt & 1;
                mma16816(acc[mt][nt], a_h, bh[ng][sl], bh[ng][sl + 2]);
                mma16816(acc[mt][nt], a_h, bl[ng][sl], bl[ng][sl + 2]);
                mma16816(acc[mt][nt], a_l, bh[ng][sl], bh[ng][sl + 2]);
            }
        }
        __syncthreads();
    }

    // ---- epilogue ----
    int g = lane >> 2, t4 = lane & 3;
    #pragma unroll
    for (int mt = 0; mt < 4; mt++) {
        #pragma unroll
        for (int nt = 0; nt < 4; nt++) {
            int cb = col0 + wn0 + nt * 8 + 2 * t4;
            if (cb >= Nout) continue;
            float b0 = 0.f, b1 = 0.f;
            if (bias) { b0 = bias[cb]; b1 = bias[cb + 1]; }
            #pragma unroll
            for (int hrow = 0; hrow < 2; hrow++) {
                int gm = row0 + wm0 + mt * 16 + g + hrow * 8;
                if (gm >= M) continue;
                float v0 = acc[mt][nt][hrow * 2 + 0] + b0;
                float v1 = acc[mt][nt][hrow * 2 + 1] + b1;
                if (act == 1) {
                    v0 = v0 / (1.f + expf(-v0));
                    v1 = v1 / (1.f + expf(-v1));
                } else if (act == 2) {
                    v0 = (v0 > 20.f) ? v0 : log1pf(expf(v0));
                    v1 = (v1 > 20.f) ? v1 : log1pf(expf(v1));
                }
                long long co = bz * sC + (long long)gm * ldc + cb;
                if (emul) { v0 *= emul[co]; v1 *= emul[co + 1]; }
                if (C) *(float2*)(C + co) = make_float2(v0, v1);
                if (Ch) {
                    __nv_bfloat16 h0, l0, h1, l1;
                    splitv(v0, h0, l0); splitv(v1, h1, l1);
                    *(__nv_bfloat162*)(Ch + co) = __nv_bfloat162(h0, h1);
                    *(__nv_bfloat162*)(Cl + co) = __nv_bfloat162(l0, l1);
                }
            }
        }
    }
}

// ---------------- pooling of x (P @ x) -> xp splits ----------------
__global__ void pool_kernel(const float* __restrict__ x)
{
    int s = blockIdx.x, b = blockIdx.y, d = threadIdx.x; // 256 threads
    int s0 = (s * Lseq) / Stok;
    int e  = ((s + 1) * Lseq + Stok - 1) / Stok;
    float acc = 0.f;
    for (int l = s0; l < e; l++) acc += x[((long long)b * Lseq + l) * Dmod + d];
    acc /= (float)(e - s0);
    long long o = ((long long)b * Stok + s) * Dmod + d;
    __nv_bfloat16 h, l2; splitv(acc, h, l2);
    g_xph[o] = h; g_xpl[o] = l2;
}

// ---------------- depthwise conv (k=4, pad 3) + SiLU -> u fp32 + splits ----------------
__global__ void conv_silu_kernel(const float* __restrict__ xi, const float* __restrict__ w,
                                 const float* __restrict__ bias, float* __restrict__ out,
                                 __nv_bfloat16* __restrict__ oh, __nv_bfloat16* __restrict__ ol,
                                 int backward)
{
    int t = blockIdx.x;
    int b = blockIdx.y;
    int c = threadIdx.x;
    float acc = bias[c];
    #pragma unroll
    for (int k = 0; k < 4; k++) {
        int i = t + k - 3;
        if (i >= 0 && i < LB) {
            int l = backward ? (Lseq - 1 - i) : i;
            acc = fmaf(w[c * 4 + k], xi[((long long)b * Lseq + l) * DI + c], acc);
        }
    }
    float r = acc / (1.f + expf(-acc));
    long long o = ((long long)b * LC + t) * DI + c;
    out[o] = r;
    __nv_bfloat16 h, l2; splitv(r, h, l2);
    oh[o] = h; ol[o] = l2;
}

// ---------------- selective scan: 16 lanes per (b,d) ----------------
__global__ __launch_bounds__(256)
void scan_kernel(const float* __restrict__ u, const float* __restrict__ delta,
                 const float* __restrict__ dbc, const float* __restrict__ A_log,
                 const float* __restrict__ Dp, float* __restrict__ y)
{
    int gid = blockIdx.x * 16 + (threadIdx.x >> 4);
    int s = threadIdx.x & 15;
    int b = gid >> 9;
    int d = gid & 511;
    float Av = -expf(A_log[d * 16 + s]);
    float Dd = Dp[d];
    float h = 0.f;
    const float* db = dbc + (long long)b * LC * NXP;
    const float* dl = delta + ((long long)b * LC) * DI + d;
    const float* uu = u     + ((long long)b * LC) * DI + d;
    float*       yy = y     + ((long long)b * LC) * DI + d;
    for (int t = 0; t < LC; t++) {
        float de = __ldg(dl + (long long)t * DI);
        float uv = __ldg(uu + (long long)t * DI);
        float Bv = __ldg(db + t * NXP + DRK + s);
        float Cv = __ldg(db + t * NXP + DRK + DS + s);
        float dA = __expf(de * Av);
        h = fmaf(dA, h, de * uv * Bv);
        float v = h * Cv;
        v += __shfl_xor_sync(0xffffffffu, v, 8);
        v += __shfl_xor_sync(0xffffffffu, v, 4);
        v += __shfl_xor_sync(0xffffffffu, v, 2);
        v += __shfl_xor_sync(0xffffffffu, v, 1);
        if (s == 0) yy[(long long)t * DI] = fmaf(Dd, uv, v);
    }
}

// ---------------- gaussian masks ----------------
__global__ void dist_kernel(const float* __restrict__ y, float* __restrict__ dist, int ref)
{
    int b = blockIdx.y;
    int t = blockIdx.x * 8 + (threadIdx.x >> 5);
    int lane = threadIdx.x & 31;
    if (t >= LC) return;
    const float* yt = y + ((long long)b * LC + t) * DI;
    const float* yr = y + ((long long)b * LC + ref) * DI;
    float acc = 0.f;
    for (int d = lane; d < DI; d += 32) {
        float df = yt[d] - yr[d];
        acc = fmaf(df, df, acc);
    }
    #pragma unroll
    for (int o = 16; o; o >>= 1) acc += __shfl_xor_sync(0xffffffffu, acc, o);
    if (lane == 0) dist[b * LC + t] = sqrtf(fmaxf(acc, 1e-12f));
}

__global__ void maskfin_kernel(const float* __restrict__ dist, float* __restrict__ m, int ref)
{
    __shared__ float red[512];
    int b = blockIdx.x;
    int tid = threadIdx.x;
    float s = 0.f;
    for (int t = tid; t < LC; t += 512) s += dist[b * LC + t];
    red[tid] = s; __syncthreads();
    for (int o = 256; o; o >>= 1) { if (tid < o) red[tid] += red[tid + o]; __syncthreads(); }
    float sigv = red[0] / (float)LC;
    __syncthreads();
    float si = ((float)ref * (float)(ref + 1) * 0.5f +
                (float)(LC - 1 - ref) * (float)(LC - ref) * 0.5f) / (float)LC;
    float c_i = 0.5f / (si * si);
    float c_v = 0.5f / (sigv * sigv);
    float nrm = 0.f;
    for (int t = tid; t < LC; t += 512) {
        float dt = (float)(t - ref);
        float dv = dist[b * LC + t];
        float p = expf(-dt * dt * c_i - dv * dv * c_v);
        m[b * LC + t] = p;
        nrm = fmaf(p, p, nrm);
    }
    red[tid] = nrm; __syncthreads();
    for (int o = 256; o; o >>= 1) { if (tid < o) red[tid] += red[tid + o]; __syncthreads(); }
    float inv = 1.f / fmaxf(sqrtf(red[0]), 1e-12f);
    __syncthreads();
    for (int t = tid; t < LC; t += 512) m[b * LC + t] *= inv;
}

// ycat = [ y_f * m_f , y_b * reverse(m_b) ]  -> bf16 splits only
__global__ void concat_kernel()
{
    int t = blockIdx.x, b = blockIdx.y, c = threadIdx.x;
    long long r = (long long)b * LC + t;
    float v0 = g_yf[r * DI + c] * g_mf[b * LC + t];
    float v1 = g_yb[r * DI + c] * g_mb[b * LC + (LC - 1 - t)];
    __nv_bfloat16 h, l;
    splitv(v0, h, l);
    g_ycat_h[r * (2 * DI) + c] = h;      g_ycat_l[r * (2 * DI) + c] = l;
    splitv(v1, h, l);
    g_ycat_h[r * (2 * DI) + DI + c] = h; g_ycat_l[r * (2 * DI) + DI + c] = l;
}

// y *= mc -> y splits (scaled)
__global__ void scale_y_kernel()
{
    int t = blockIdx.x, b = blockIdx.y, c = threadIdx.x;
    long long r = (long long)b * LC + t;
    float v = g_y[r * DI + c] * g_mc[b * LC + t];
    __nv_bfloat16 h, l; splitv(v, h, l);
    g_yh[r * DI + c] = h; g_yl[r * DI + c] = l;
}

// softmax over l per (b, token); writes Atok splits (B, Stok, LCP) zero-padded
__global__ void softmax_kernel()
{
    __shared__ float sv[LC];
    __shared__ float red[256];
    int tt = blockIdx.x, b = blockIdx.y, tid = threadIdx.x;
    float mx = -1e30f;
    for (int l = tid; l < LC; l += 256) {
        float v = g_scores[((long long)b * LC + l) * Stok + tt];
        sv[l] = v; mx = fmaxf(mx, v);
    }
    red[tid] = mx; __syncthreads();
    for (int o = 128; o; o >>= 1) { if (tid < o) red[tid] = fmaxf(red[tid], red[tid + o]); __syncthreads(); }
    mx = red[0]; __syncthreads();
    float sum = 0.f;
    for (int l = tid; l < LC; l += 256) { float e = expf(sv[l] - mx); sv[l] = e; sum += e; }
    red[tid] = sum; __syncthreads();
    for (int o = 128; o; o >>= 1) { if (tid < o) red[tid] += red[tid + o]; __syncthreads(); }
    float inv = 1.f / red[0]; __syncthreads();
    long long base = ((long long)b * Stok + tt) * LCP;
    for (int l = tid; l < LC; l += 256) {
        float v = sv[l] * inv;
        __nv_bfloat16 h, lo; splitv(v, h, lo);
        g_akh[base + l] = h; g_akl[base + l] = lo;
    }
    if (tid < LCP - LC) {
        g_akh[base + LC + tid] = __float2bfloat16(0.f);
        g_akl[base + LC + tid] = __float2bfloat16(0.f);
    }
}

// ---------------- host launcher ----------------
static inline int ceildiv(int a, int b) { return (a + b - 1) / b; }

extern "C" void kernel_launch(void* const* d_in, const int* in_sizes, int n_in,
                              void* d_out, int out_size)
{
    const float* x        = (const float*)d_in[0];
    const float* W_in_x   = (const float*)d_in[1];
    const float* W_in_z   = (const float*)d_in[2];
    const float* conv_w_f = (const float*)d_in[3];
    const float* conv_b_f = (const float*)d_in[4];
    const float* conv_w_b = (const float*)d_in[5];
    const float* conv_b_b = (const float*)d_in[6];
    const float* W_xp_f   = (const float*)d_in[7];
    const float* b_xp_f   = (const float*)d_in[8];
    const float* W_dt_f   = (const float*)d_in[9];
    const float* b_dt_f   = (const float*)d_in[10];
    const float* A_log_f  = (const float*)d_in[11];
    const float* D_f      = (const float*)d_in[12];
    const float* W_xp_b   = (const float*)d_in[13];
    const float* b_xp_b   = (const float*)d_in[14];
    const float* W_dt_b   = (const float*)d_in[15];
    const float* b_dt_b   = (const float*)d_in[16];
    const float* A_log_b  = (const float*)d_in[17];
    const float* D_b      = (const float*)d_in[18];
    const float* W_pro_to = (const float*)d_in[19];
    const float* b_pro_to = (const float*)d_in[20];
    const float* token_wA = (const float*)d_in[21];
    const float* token_wV = (const float*)d_in[22];
    const float* W_out    = (const float*)d_in[23];
    float* out = (float*)d_out;

    // fp32 scratch addrs
    float *xi, *uf, *ub, *dbcf, *dbcb, *def, *deb, *yf, *yb, *yy;
    float *mf, *mb, *mc, *dist, *zp, *scores;
    cudaGetSymbolAddress((void**)&xi,   g_xi);
    cudaGetSymbolAddress((void**)&uf,   g_uf);
    cudaGetSymbolAddress((void**)&ub,   g_ub);
    cudaGetSymbolAddress((void**)&dbcf, g_dbcf);
    cudaGetSymbolAddress((void**)&dbcb, g_dbcb);
    cudaGetSymbolAddress((void**)&def,  g_deltaf);
    cudaGetSymbolAddress((void**)&deb,  g_deltab);
    cudaGetSymbolAddress((void**)&yf,   g_yf);
    cudaGetSymbolAddress((void**)&yb,   g_yb);
    cudaGetSymbolAddress((void**)&yy,   g_y);
    cudaGetSymbolAddress((void**)&mf,   g_mf);
    cudaGetSymbolAddress((void**)&mb,   g_mb);
    cudaGetSymbolAddress((void**)&mc,   g_mc);
    cudaGetSymbolAddress((void**)&dist, g_dist);
    cudaGetSymbolAddress((void**)&zp,   g_zp);
    cudaGetSymbolAddress((void**)&scores, g_scores);

    // bf16 plane addrs
    __nv_bfloat16 *xh,*xl, *Winxh,*Winxl, *Winzh,*Winzl, *xph,*xpl;
    __nv_bfloat16 *ufh,*ufl, *ubh,*ubl, *Wxpfh,*Wxpfl, *Wxpbh,*Wxpbl;
    __nv_bfloat16 *dbcfh,*dbcfl, *dbcbh,*dbcbl, *Wdtfh,*Wdtfl, *Wdtbh,*Wdtbl;
    __nv_bfloat16 *ycath,*ycatl, *Wproh,*Wprol, *yh2,*yl2, *wAh,*wAl;
    __nv_bfloat16 *akh,*akl, *tyh,*tyl, *wVh,*wVl, *Th,*Tl, *Wouth,*Woutl;
    cudaGetSymbolAddress((void**)&xh, g_xh);     cudaGetSymbolAddress((void**)&xl, g_xl);
    cudaGetSymbolAddress((void**)&Winxh, g_Winx_h); cudaGetSymbolAddress((void**)&Winxl, g_Winx_l);
    cudaGetSymbolAddress((void**)&Winzh, g_Winz_h); cudaGetSymbolAddress((void**)&Winzl, g_Winz_l);
    cudaGetSymbolAddress((void**)&xph, g_xph);   cudaGetSymbolAddress((void**)&xpl, g_xpl);
    cudaGetSymbolAddress((void**)&ufh, g_ufh);   cudaGetSymbolAddress((void**)&ufl, g_ufl);
    cudaGetSymbolAddress((void**)&ubh, g_ubh);   cudaGetSymbolAddress((void**)&ubl, g_ubl);
    cudaGetSymbolAddress((void**)&Wxpfh, g_Wxpf_h); cudaGetSymbolAddress((void**)&Wxpfl, g_Wxpf_l);
    cudaGetSymbolAddress((void**)&Wxpbh, g_Wxpb_h); cudaGetSymbolAddress((void**)&Wxpbl, g_Wxpb_l);
    cudaGetSymbolAddress((void**)&dbcfh, g_dbcfh); cudaGetSymbolAddress((void**)&dbcfl, g_dbcfl);
    cudaGetSymbolAddress((void**)&dbcbh, g_dbcbh); cudaGetSymbolAddress((void**)&dbcbl, g_dbcbl);
    cudaGetSymbolAddress((void**)&Wdtfh, g_Wdtf_h); cudaGetSymbolAddress((void**)&Wdtfl, g_Wdtf_l);
    cudaGetSymbolAddress((void**)&Wdtbh, g_Wdtb_h); cudaGetSymbolAddress((void**)&Wdtbl, g_Wdtb_l);
    cudaGetSymbolAddress((void**)&ycath, g_ycat_h); cudaGetSymbolAddress((void**)&ycatl, g_ycat_l);
    cudaGetSymbolAddress((void**)&Wproh, g_Wpro_h); cudaGetSymbolAddress((void**)&Wprol, g_Wpro_l);
    cudaGetSymbolAddress((void**)&yh2, g_yh);    cudaGetSymbolAddress((void**)&yl2, g_yl);
    cudaGetSymbolAddress((void**)&wAh, g_wA_h);  cudaGetSymbolAddress((void**)&wAl, g_wA_l);
    cudaGetSymbolAddress((void**)&akh, g_akh);   cudaGetSymbolAddress((void**)&akl, g_akl);
    cudaGetSymbolAddress((void**)&tyh, g_tyh);   cudaGetSymbolAddress((void**)&tyl, g_tyl);
    cudaGetSymbolAddress((void**)&wVh, g_wV_h);  cudaGetSymbolAddress((void**)&wVl, g_wV_l);
    cudaGetSymbolAddress((void**)&Th, g_Th);     cudaGetSymbolAddress((void**)&Tl, g_Tl);
    cudaGetSymbolAddress((void**)&Wouth, g_Wout_h); cudaGetSymbolAddress((void**)&Woutl, g_Wout_l);

    const int ML = Bsz * Lseq;  // 16392
    const int MC = Bsz * LC;    // 8224

    // ---- weight / input splits ----
    split_kernel<<<ceildiv(ML * Dmod, 256), 256>>>(x, xh, xl, ML * Dmod);
    split_kernel<<<ceildiv(DI * Dmod, 256), 256>>>(W_in_x, Winxh, Winxl, DI * Dmod);
    split_kernel<<<ceildiv(DI * Dmod, 256), 256>>>(W_in_z, Winzh, Winzl, DI * Dmod);
    split_pad_kernel<<<ceildiv(128 * DI, 256), 256>>>(W_xp_f, Wxpfh, Wxpfl, NXP, DI, 128);
    split_pad_kernel<<<ceildiv(128 * DI, 256), 256>>>(W_xp_b, Wxpbh, Wxpbl, NXP, DI, 128);
    split_kernel<<<ceildiv(DI * DRK, 256), 256>>>(W_dt_f, Wdtfh, Wdtfl, DI * DRK);
    split_kernel<<<ceildiv(DI * DRK, 256), 256>>>(W_dt_b, Wdtbh, Wdtbl, DI * DRK);
    split_kernel<<<ceildiv(DI * 2 * DI, 256), 256>>>(W_pro_to, Wproh, Wprol, DI * 2 * DI);
    split_pad_kernel<<<ceildiv(128 * DI, 256), 256>>>(token_wA, wAh, wAl, Stok, DI, 128);
    split_kernel<<<ceildiv(DI * DI, 256), 256>>>(token_wV, wVh, wVl, DI * DI);
    split_kernel<<<ceildiv(Dmod * DI, 256), 256>>>(W_out, Wouth, Woutl, Dmod * DI);

    // 1) xi = x @ W_in_x^T  (fp32 out)
    hgemm2<1><<<dim3(DI / 128, ceildiv(ML, 128)), 256>>>(
        xh, xl, Winxh, Winxl, nullptr, nullptr, xi, nullptr, nullptr,
        ML, DI, Dmod, Dmod, Dmod, DI, DI, 0, 0, 0, 0);

    // 2) xp pooling, zp = silu(xp @ W_in_z^T)
    pool_kernel<<<dim3(Stok, Bsz), Dmod>>>(x);
    hgemm2<1><<<dim3(DI / 128, 4), 256>>>(
        xph, xpl, Winzh, Winzl, nullptr, nullptr, zp, nullptr, nullptr,
        Bsz * Stok, DI, Dmod, Dmod, Dmod, DI, DI, 1, 0, 0, 0);

    // 3) conv + silu (fp32 + splits)
    conv_silu_kernel<<<dim3(LC, Bsz), DI>>>(xi, conv_w_f, conv_b_f, uf, ufh, ufl, 0);
    conv_silu_kernel<<<dim3(LC, Bsz), DI>>>(xi, conv_w_b, conv_b_b, ub, ubh, ubl, 1);

    // 4) dbc = u @ W_xp^T + b  (N padded 128, Nout 48, fp32 + splits)
    hgemm2<1><<<dim3(1, ceildiv(MC, 128)), 256>>>(
        ufh, ufl, Wxpfh, Wxpfl, b_xp_f, nullptr, dbcf, dbcfh, dbcfl,
        MC, 128, DI, DI, DI, NXP, NXP, 0, 0, 0, 0);
    hgemm2<1><<<dim3(1, ceildiv(MC, 128)), 256>>>(
        ubh, ubl, Wxpbh, Wxpbl, b_xp_b, nullptr, dbcb, dbcbh, dbcbl,
        MC, 128, DI, DI, DI, NXP, NXP, 0, 0, 0, 0);

    // 5) delta = softplus(dr @ W_dt^T + b_dt)  (K=16, fp32 out)
    hgemm2<1><<<dim3(DI / 128, ceildiv(MC, 128)), 256>>>(
        dbcfh, dbcfl, Wdtfh, Wdtfl, b_dt_f, nullptr, def, nullptr, nullptr,
        MC, DI, DRK, NXP, DRK, DI, DI, 2, 0, 0, 0);
    hgemm2<1><<<dim3(DI / 128, ceildiv(MC, 128)), 256>>>(
        dbcbh, dbcbl, Wdtbh, Wdtbl, b_dt_b, nullptr, deb, nullptr, nullptr,
        MC, DI, DRK, NXP, DRK, DI, DI, 2, 0, 0, 0);

    // 6) selective scans
    scan_kernel<<<Bsz * DI / 16, 256>>>(uf, def, dbcf, A_log_f, D_f, yf);
    scan_kernel<<<Bsz * DI / 16, 256>>>(ub, deb, dbcb, A_log_b, D_b, yb);

    // 7) masks ('last')
    dist_kernel<<<dim3(ceildiv(LC, 8), Bsz), 256>>>(yf, dist, LC - 1);
    maskfin_kernel<<<Bsz, 512>>>(dist, mf, LC - 1);
    dist_kernel<<<dim3(ceildiv(LC, 8), Bsz), 256>>>(yb, dist, LC - 1);
    maskfin_kernel<<<Bsz, 512>>>(dist, mb, LC - 1);

    // 8) ycat splits, y = ycat @ W_pro^T + b (fp32)
    concat_kernel<<<dim3(LC, Bsz), DI>>>();
    hgemm2<1><<<dim3(DI / 128, ceildiv(MC, 128)), 256>>>(
        ycath, ycatl, Wproh, Wprol, b_pro_to, nullptr, yy, nullptr, nullptr,
        MC, DI, 2 * DI, 2 * DI, 2 * DI, DI, DI, 0, 0, 0, 0);

    // 9) center mask, scaled y splits
    dist_kernel<<<dim3(ceildiv(LC, 8), Bsz), 256>>>(yy, dist, (LC + 1) / 2);
    maskfin_kernel<<<Bsz, 512>>>(dist, mc, (LC + 1) / 2);
    scale_y_kernel<<<dim3(LC, Bsz), DI>>>();

    // 10) scores = y @ wA^T (N pad 128, Nout 64), softmax -> atok splits
    hgemm2<1><<<dim3(1, ceildiv(MC, 128)), 256>>>(
        yh2, yl2, wAh, wAl, nullptr, nullptr, scores, nullptr, nullptr,
        MC, 128, DI, DI, DI, Stok, Stok, 0, 0, 0, 0);
    softmax_kernel<<<dim3(Stok, Bsz), 256>>>();

    // 11) Ty = Atok @ y  (TB=0, batched, K padded to 1040, splits out)
    hgemm2<0><<<dim3(DI / 128, 1, Bsz), 256>>>(
        akh, akl, yh2, yl2, nullptr, nullptr, nullptr, tyh, tyl,
        Stok, DI, LCP, LCP, DI, DI, DI, 0,
        (long long)Stok * LCP, (long long)LC * DI, (long long)Stok * DI);

    // 12) T = (Ty @ wV) * zp  (TB=0, batched, splits out)
    hgemm2<0><<<dim3(DI / 128, 1, Bsz), 256>>>(
        tyh, tyl, wVh, wVl, nullptr, zp, nullptr, Th, Tl,
        Stok, DI, DI, DI, DI, DI, DI, 0,
        (long long)Stok * DI, 0, (long long)Stok * DI);

    // 13) out = T @ W_out^T
    hgemm2<1><<<dim3(Dmod / 128, ceildiv(Bsz * Stok, 128)), 256>>>(
        Th, Tl, Wouth, Woutl, nullptr, nullptr, out, nullptr, nullptr,
        Bsz * Stok, Dmod, DI, DI, DI, Dmod, Dmod, 0, 0, 0, 0);
}

// round 5
// speedup vs baseline: 1.3568x; 1.3568x over previous
#include <cuda_runtime.h>
#include <cuda_bf16.h>
#include <math.h>
#include <stdint.h>

// ---------------- problem constants ----------------
#define Bsz  8
#define Lseq 2049
#define Dmod 256
#define DI   512
#define DS   16
#define DRK  16
#define LB   1025
#define LC   1028
#define Stok 64
#define NXP  48
#define LCP  1040   // LC padded to 16

// ---------------- fp32 scratch ----------------
__device__ float g_xi[Bsz*Lseq*DI];
__device__ float g_uf[Bsz*LC*DI];
__device__ float g_ub[Bsz*LC*DI];
__device__ float g_dbcf[Bsz*LC*NXP];
__device__ float g_dbcb[Bsz*LC*NXP];
__device__ float g_deltaf[Bsz*LC*DI];
__device__ float g_deltab[Bsz*LC*DI];
__device__ float g_yf[Bsz*LC*DI];
__device__ float g_yb[Bsz*LC*DI];
__device__ float g_ycat[Bsz*LC*2*DI];
__device__ float g_y[Bsz*LC*DI];
__device__ float g_mf[Bsz*LC];
__device__ float g_mb[Bsz*LC];
__device__ float g_mc[Bsz*LC];
__device__ float g_dist[Bsz*LC*2];
__device__ float g_xpf[Bsz*Stok*Dmod];
__device__ float g_zp[Bsz*Stok*DI];
__device__ float g_scores[Bsz*LC*Stok];
__device__ float g_atok[Bsz*Stok*LCP];
__device__ float g_ty[Bsz*Stok*DI];
__device__ float g_T[Bsz*Stok*DI];

// ---------------- bf16 weight planes (+ y planes for TB=0 use) ----------------
__device__ __nv_bfloat16 g_Winx_h[DI*Dmod],     g_Winx_l[DI*Dmod];
__device__ __nv_bfloat16 g_Winz_h[DI*Dmod],     g_Winz_l[DI*Dmod];
__device__ __nv_bfloat16 g_Wxpf_h[128*DI],      g_Wxpf_l[128*DI];
__device__ __nv_bfloat16 g_Wxpb_h[128*DI],      g_Wxpb_l[128*DI];
__device__ __nv_bfloat16 g_Wdtf_h[DI*DRK],      g_Wdtf_l[DI*DRK];
__device__ __nv_bfloat16 g_Wdtb_h[DI*DRK],      g_Wdtb_l[DI*DRK];
__device__ __nv_bfloat16 g_Wpro_h[DI*2*DI],     g_Wpro_l[DI*2*DI];
__device__ __nv_bfloat16 g_wA_h[128*DI],        g_wA_l[128*DI];
__device__ __nv_bfloat16 g_wV_h[DI*DI],         g_wV_l[DI*DI];
__device__ __nv_bfloat16 g_Wout_h[Dmod*DI],     g_Wout_l[Dmod*DI];
__device__ __nv_bfloat16 g_yh[Bsz*LC*DI+16*DI], g_yl[Bsz*LC*DI+16*DI]; // slack rows stay 0

__device__ __forceinline__ void splitv(float v, __nv_bfloat16& h, __nv_bfloat16& l) {
    h = __float2bfloat16(v);
    l = __float2bfloat16(v - __bfloat162float(h));
}

// ---------------- fused weight split (one launch) ----------------
__global__ void wsplit_kernel(const float* __restrict__ Winx, const float* __restrict__ Winz,
                              const float* __restrict__ Wxpf, const float* __restrict__ Wxpb,
                              const float* __restrict__ Wdtf, const float* __restrict__ Wdtb,
                              const float* __restrict__ Wpro, const float* __restrict__ wA,
                              const float* __restrict__ wV,   const float* __restrict__ Wout)
{
    int i = blockIdx.x * 256 + threadIdx.x;
    __nv_bfloat16 h, l;
    if (i < 131072) { splitv(Winx[i], h, l); g_Winx_h[i] = h; g_Winx_l[i] = l; return; }
    i -= 131072;
    if (i < 131072) { splitv(Winz[i], h, l); g_Winz_h[i] = h; g_Winz_l[i] = l; return; }
    i -= 131072;
    if (i < 65536) { int r = i >> 9, c = i & 511;
        splitv(r < NXP ? Wxpf[r * DI + c] : 0.f, h, l);
        g_Wxpf_h[i] = h; g_Wxpf_l[i] = l; return; }
    i -= 65536;
    if (i < 65536) { int r = i >> 9, c = i & 511;
        splitv(r < NXP ? Wxpb[r * DI + c] : 0.f, h, l);
        g_Wxpb_h[i] = h; g_Wxpb_l[i] = l; return; }
    i -= 65536;
    if (i < 8192) { splitv(Wdtf[i], h, l); g_Wdtf_h[i] = h; g_Wdtf_l[i] = l; return; }
    i -= 8192;
    if (i < 8192) { splitv(Wdtb[i], h, l); g_Wdtb_h[i] = h; g_Wdtb_l[i] = l; return; }
    i -= 8192;
    if (i < 524288) { splitv(Wpro[i], h, l); g_Wpro_h[i] = h; g_Wpro_l[i] = l; return; }
    i -= 524288;
    if (i < 65536) { int r = i >> 9, c = i & 511;
        splitv(r < Stok ? wA[r * DI + c] : 0.f, h, l);
        g_wA_h[i] = h; g_wA_l[i] = l; return; }
    i -= 65536;
    if (i < 262144) { splitv(wV[i], h, l); g_wV_h[i] = h; g_wV_l[i] = l; return; }
    i -= 262144;
    if (i < 131072) { splitv(Wout[i], h, l); g_Wout_h[i] = h; g_Wout_l[i] = l; }
}
#define WSPLIT_TOT 1392640

// =====================================================================
// hgemm3: C = A(fp32, M x K) * op(B pre-split bf16 planes), 3-split MMA.
// TB=1: B planes are (N,K) row-major; TB=0: (K,N) row-major.
// N % 128 == 0 (buffer domain), writes guarded by Nout; K % 16 == 0.
// lda % 4 == 0, ldb % 8 == 0. act: 0/1 silu/2 softplus. emul gate.
// Register-prefetch single-buffer smem pipeline.
// =====================================================================
#define SAS 24

__device__ __forceinline__ uint32_t s2u(const void* p) {
    return (uint32_t)__cvta_generic_to_shared(p);
}
__device__ __forceinline__ void ldsm4(uint32_t r[4], uint32_t addr) {
    asm volatile("ldmatrix.sync.aligned.m8n8.x4.shared.b16 {%0,%1,%2,%3}, [%4];"
                 : "=r"(r[0]), "=r"(r[1]), "=r"(r[2]), "=r"(r[3]) : "r"(addr));
}
__device__ __forceinline__ void mma16816(float c[4], const uint32_t a[4],
                                         uint32_t b0, uint32_t b1) {
    asm volatile(
        "mma.sync.aligned.m16n8k16.row.col.f32.bf16.bf16.f32 "
        "{%0,%1,%2,%3},{%4,%5,%6,%7},{%8,%9},{%0,%1,%2,%3};"
        : "+f"(c[0]), "+f"(c[1]), "+f"(c[2]), "+f"(c[3])
        : "r"(a[0]), "r"(a[1]), "r"(a[2]), "r"(a[3]), "r"(b0), "r"(b1));
}

template<int TB>
__global__ __launch_bounds__(256, 2)
void hgemm3(const float* __restrict__ A,
            const __nv_bfloat16* __restrict__ Bh, const __nv_bfloat16* __restrict__ Bl,
            const float* __restrict__ bias, const float* __restrict__ emul,
            float* __restrict__ C,
            int M, int N, int K, int lda, int ldb, int ldc, int Nout, int act,
            long long sA, long long sB, long long sC)
{
    __shared__ __align__(16) __nv_bfloat16 As_hi[128][SAS];
    __shared__ __align__(16) __nv_bfloat16 As_lo[128][SAS];
    __shared__ __align__(16) __nv_bfloat16 Bs_hi[128][SAS];
    __shared__ __align__(16) __nv_bfloat16 Bs_lo[128][SAS];

    int bz = blockIdx.z;
    A  += bz * sA;
    Bh += bz * sB; Bl += bz * sB;

    int tid  = threadIdx.x;
    int lane = tid & 31;
    int wid  = tid >> 5;
    int wm0  = (wid >> 2) * 64;
    int wn0  = (wid & 3) * 32;
    int row0 = blockIdx.y * 128;
    int col0 = blockIdx.x * 128;

    int lr = lane & 15;
    int lc = (lane >> 4) * 8;

    // load mapping
    int ar = tid >> 1;          // 0..127
    int ac = (tid & 1) * 8;     // 0 or 8
    int gm = row0 + ar;
    bool mok = gm < M;
    const float* Ap = A + (long long)gm * lda + ac;
    const __nv_bfloat16 *Bph, *Bpl;
    int bkk = 0, bnc = 0;
    if (TB == 1) {
        Bph = Bh + (long long)(col0 + ar) * ldb + ac;
        Bpl = Bl + (long long)(col0 + ar) * ldb + ac;
    } else {
        bkk = tid >> 4;           // 0..15
        bnc = (tid & 15) * 8;     // 0..120
        Bph = Bh + (long long)bkk * ldb + col0 + bnc;
        Bpl = Bl + (long long)bkk * ldb + col0 + bnc;
    }

    float4 ra0 = make_float4(0,0,0,0), ra1 = make_float4(0,0,0,0);
    uint4 rbh, rbl;

    // preload k0 = 0
    if (mok) { ra0 = *(const float4*)(Ap); ra1 = *(const float4*)(Ap + 4); }
    if (TB == 1) { rbh = *(const uint4*)(Bph); rbl = *(const uint4*)(Bpl); }
    else         { rbh = *(const uint4*)(Bph); rbl = *(const uint4*)(Bpl); }

    float acc[4][4][4];
    #pragma unroll
    for (int i = 0; i < 4; i++)
        #pragma unroll
        for (int j = 0; j < 4; j++)
            #pragma unroll
            for (int q = 0; q < 4; q++) acc[i][j][q] = 0.f;

    for (int k0 = 0; k0 < K; k0 += 16) {
        // ---- store current regs to smem (A converted here) ----
        {
            float av[8] = {ra0.x, ra0.y, ra0.z, ra0.w, ra1.x, ra1.y, ra1.z, ra1.w};
            __nv_bfloat16 hh[8], ll[8];
            #pragma unroll
            for (int j = 0; j < 8; j++) splitv(av[j], hh[j], ll[j]);
            *(uint4*)&As_hi[ar][ac] = *(uint4*)hh;
            *(uint4*)&As_lo[ar][ac] = *(uint4*)ll;
        }
        if (TB == 1) {
            *(uint4*)&Bs_hi[ar][ac] = rbh;
            *(uint4*)&Bs_lo[ar][ac] = rbl;
        } else {
            __nv_bfloat16 th[8], tl[8];
            *(uint4*)th = rbh; *(uint4*)tl = rbl;
            #pragma unroll
            for (int j = 0; j < 8; j++) {
                Bs_hi[bnc + j][bkk] = th[j];
                Bs_lo[bnc + j][bkk] = tl[j];
            }
        }
        __syncthreads();

        // ---- prefetch next tile ----
        if (k0 + 16 < K) {
            if (mok) {
                ra0 = *(const float4*)(Ap + k0 + 16);
                ra1 = *(const float4*)(Ap + k0 + 20);
            }
            if (TB == 1) {
                rbh = *(const uint4*)(Bph + k0 + 16);
                rbl = *(const uint4*)(Bpl + k0 + 16);
            } else {
                rbh = *(const uint4*)(Bph + (long long)(k0 + 16) * ldb);
                rbl = *(const uint4*)(Bpl + (long long)(k0 + 16) * ldb);
            }
        }

        // ---- MMAs ----
        uint32_t bhf[2][4], blf[2][4];
        #pragma unroll
        for (int ng = 0; ng < 2; ng++) {
            ldsm4(bhf[ng], s2u(&Bs_hi[wn0 + ng * 16 + lr][lc]));
            ldsm4(blf[ng], s2u(&Bs_lo[wn0 + ng * 16 + lr][lc]));
        }
        #pragma unroll
        for (int mt = 0; mt < 4; mt++) {
            uint32_t a_h[4], a_l[4];
            ldsm4(a_h, s2u(&As_hi[wm0 + mt * 16 + lr][lc]));
            ldsm4(a_l, s2u(&As_lo[wm0 + mt * 16 + lr][lc]));
            #pragma unroll
            for (int nt = 0; nt < 4; nt++) {
                int ng = nt >> 1, sl = nt & 1;
                mma16816(acc[mt][nt], a_h, bhf[ng][sl], bhf[ng][sl + 2]);
                mma16816(acc[mt][nt], a_h, blf[ng][sl], blf[ng][sl + 2]);
                mma16816(acc[mt][nt], a_l, bhf[ng][sl], bhf[ng][sl + 2]);
            }
        }
        __syncthreads();
    }

    // ---- epilogue ----
    int g = lane >> 2, t4 = lane & 3;
    #pragma unroll
    for (int mt = 0; mt < 4; mt++) {
        #pragma unroll
        for (int nt = 0; nt < 4; nt++) {
            int cb = col0 + wn0 + nt * 8 + 2 * t4;
            if (cb >= Nout) continue;
            float b0 = 0.f, b1 = 0.f;
            if (bias) { b0 = bias[cb]; b1 = bias[cb + 1]; }
            #pragma unroll
            for (int hrow = 0; hrow < 2; hrow++) {
                int m = row0 + wm0 + mt * 16 + g + hrow * 8;
                if (m >= M) continue;
                float v0 = acc[mt][nt][hrow * 2 + 0] + b0;
                float v1 = acc[mt][nt][hrow * 2 + 1] + b1;
                if (act == 1) {
                    v0 = v0 / (1.f + expf(-v0));
                    v1 = v1 / (1.f + expf(-v1));
                } else if (act == 2) {
                    v0 = (v0 > 20.f) ? v0 : log1pf(expf(v0));
                    v1 = (v1 > 20.f) ? v1 : log1pf(expf(v1));
                }
                long long co = bz * sC + (long long)m * ldc + cb;
                if (emul) { v0 *= emul[co]; v1 *= emul[co + 1]; }
                *(float2*)(C + co) = make_float2(v0, v1);
            }
        }
    }
}

// ---------------- pooling of x (P @ x) -> fp32 ----------------
__global__ void pool_kernel(const float* __restrict__ x)
{
    int s = blockIdx.x, b = blockIdx.y, d = threadIdx.x;
    int s0 = (s * Lseq) / Stok;
    int e  = ((s + 1) * Lseq + Stok - 1) / Stok;
    float acc = 0.f;
    for (int l = s0; l < e; l++) acc += x[((long long)b * Lseq + l) * Dmod + d];
    g_xpf[((long long)b * Stok + s) * Dmod + d] = acc / (float)(e - s0);
}

// ---------------- depthwise conv + SiLU, both directions in one launch ----------------
__global__ void conv_silu2_kernel(const float* __restrict__ xi,
                                  const float* __restrict__ wf, const float* __restrict__ bf,
                                  const float* __restrict__ wb, const float* __restrict__ bb)
{
    int t = blockIdx.x;
    int b = blockIdx.y;
    int back = blockIdx.z;
    int c = threadIdx.x;
    const float* w  = back ? wb : wf;
    float acc       = back ? bb[c] : bf[c];
    float* out      = back ? g_ub : g_uf;
    #pragma unroll
    for (int k = 0; k < 4; k++) {
        int i = t + k - 3;
        if (i >= 0 && i < LB) {
            int l = back ? (Lseq - 1 - i) : i;
            acc = fmaf(w[c * 4 + k], xi[((long long)b * Lseq + l) * DI + c], acc);
        }
    }
    out[((long long)b * LC + t) * DI + c] = acc / (1.f + expf(-acc));
}

// ---------------- selective scans, both directions in one launch ----------------
__global__ __launch_bounds__(256)
void scan2_kernel(const float* __restrict__ A_log_f, const float* __restrict__ D_f,
                  const float* __restrict__ A_log_b, const float* __restrict__ D_b)
{
    int back = blockIdx.y;
    const float* u     = back ? g_ub : g_uf;
    const float* delta = back ? g_deltab : g_deltaf;
    const float* dbc   = back ? g_dbcb : g_dbcf;
    const float* A_log = back ? A_log_b : A_log_f;
    const float* Dp    = back ? D_b : D_f;
    float* y           = back ? g_yb : g_yf;

    int gid = blockIdx.x * 16 + (threadIdx.x >> 4);
    int s = threadIdx.x & 15;
    int b = gid >> 9;
    int d = gid & 511;
    float Av = -expf(A_log[d * 16 + s]);
    float Dd = Dp[d];
    float h = 0.f;
    const float* db = dbc + (long long)b * LC * NXP;
    const float* dl = delta + ((long long)b * LC) * DI + d;
    const float* uu = u     + ((long long)b * LC) * DI + d;
    float*       yy = y     + ((long long)b * LC) * DI + d;
    for (int t = 0; t < LC; t++) {
        float de = __ldg(dl + (long long)t * DI);
        float uv = __ldg(uu + (long long)t * DI);
        float Bv = __ldg(db + t * NXP + DRK + s);
        float Cv = __ldg(db + t * NXP + DRK + DS + s);
        float dA = __expf(de * Av);
        h = fmaf(dA, h, de * uv * Bv);
        float v = h * Cv;
        v += __shfl_xor_sync(0xffffffffu, v, 8);
        v += __shfl_xor_sync(0xffffffffu, v, 4);
        v += __shfl_xor_sync(0xffffffffu, v, 2);
        v += __shfl_xor_sync(0xffffffffu, v, 1);
        if (s == 0) yy[(long long)t * DI] = fmaf(Dd, uv, v);
    }
}

// ---------------- gaussian masks ----------------
__global__ void dist2_kernel(int ref)   // yf and yb in one launch
{
    int back = blockIdx.z;
    const float* y = back ? g_yb : g_yf;
    float* dist = g_dist + back * (Bsz * LC);
    int b = blockIdx.y;
    int t = blockIdx.x * 8 + (threadIdx.x >> 5);
    int lane = threadIdx.x & 31;
    if (t >= LC) return;
    const float* yt = y + ((long long)b * LC + t) * DI;
    const float* yr = y + ((long long)b * LC + ref) * DI;
    float acc = 0.f;
    for (int d = lane; d < DI; d += 32) {
        float df = yt[d] - yr[d];
        acc = fmaf(df, df, acc);
    }
    #pragma unroll
    for (int o = 16; o; o >>= 1) acc += __shfl_xor_sync(0xffffffffu, acc, o);
    if (lane == 0) dist[b * LC + t] = sqrtf(fmaxf(acc, 1e-12f));
}

__global__ void dist_kernel(const float* __restrict__ y, float* __restrict__ dist, int ref)
{
    int b = blockIdx.y;
    int t = blockIdx.x * 8 + (threadIdx.x >> 5);
    int lane = threadIdx.x & 31;
    if (t >= LC) return;
    const float* yt = y + ((long long)b * LC + t) * DI;
    const float* yr = y + ((long long)b * LC + ref) * DI;
    float acc = 0.f;
    for (int d = lane; d < DI; d += 32) {
        float df = yt[d] - yr[d];
        acc = fmaf(df, df, acc);
    }
    #pragma unroll
    for (int o = 16; o; o >>= 1) acc += __shfl_xor_sync(0xffffffffu, acc, o);
    if (lane == 0) dist[b * LC + t] = sqrtf(fmaxf(acc, 1e-12f));
}

__device__ __forceinline__ void maskfin_body(const float* dist, float* m, int ref,
                                             float* red, int tid)
{
    float s = 0.f;
    for (int t = tid; t < LC; t += 512) s += dist[t];
    red[tid] = s; __syncthreads();
    for (int o = 256; o; o >>= 1) { if (tid < o) red[tid] += red[tid + o]; __syncthreads(); }
    float sigv = red[0] / (float)LC;
    __syncthreads();
    float si = ((float)ref * (float)(ref + 1) * 0.5f +
                (float)(LC - 1 - ref) * (float)(LC - ref) * 0.5f) / (float)LC;
    float c_i = 0.5f / (si * si);
    float c_v = 0.5f / (sigv * sigv);
    float nrm = 0.f;
    for (int t = tid; t < LC; t += 512) {
        float dt = (float)(t - ref);
        float dv = dist[t];
        float p = expf(-dt * dt * c_i - dv * dv * c_v);
        m[t] = p;
        nrm = fmaf(p, p, nrm);
    }
    red[tid] = nrm; __syncthreads();
    for (int o = 256; o; o >>= 1) { if (tid < o) red[tid] += red[tid + o]; __syncthreads(); }
    float inv = 1.f / fmaxf(sqrtf(red[0]), 1e-12f);
    __syncthreads();
    for (int t = tid; t < LC; t += 512) m[t] *= inv;
}

__global__ void maskfin2_kernel(int ref)   // m_f and m_b in one launch
{
    __shared__ float red[512];
    int back = blockIdx.y;
    int b = blockIdx.x;
    const float* dist = g_dist + back * (Bsz * LC) + b * LC;
    float* m = (back ? g_mb : g_mf) + b * LC;
    maskfin_body(dist, m, ref, red, threadIdx.x);
}

__global__ void maskfin_kernel(const float* __restrict__ dist, float* __restrict__ m, int ref)
{
    __shared__ float red[512];
    int b = blockIdx.x;
    maskfin_body(dist + b * LC, m + b * LC, ref, red, threadIdx.x);
}

// ycat = [ y_f * m_f , y_b * reverse(m_b) ]  (fp32)
__global__ void concat_kernel()
{
    int t = blockIdx.x, b = blockIdx.y, c = threadIdx.x;
    long long r = (long long)b * LC + t;
    g_ycat[r * (2 * DI) + c]      = g_yf[r * DI + c] * g_mf[b * LC + t];
    g_ycat[r * (2 * DI) + DI + c] = g_yb[r * DI + c] * g_mb[b * LC + (LC - 1 - t)];
}

// y *= mc (in place fp32) + bf16 split planes for TB=0 B-side use
__global__ void scale_y_kernel()
{
    int t = blockIdx.x, b = blockIdx.y, c = threadIdx.x;
    long long r = (long long)b * LC + t;
    float v = g_y[r * DI + c] * g_mc[b * LC + t];
    g_y[r * DI + c] = v;
    __nv_bfloat16 h, l; splitv(v, h, l);
    g_yh[r * DI + c] = h; g_yl[r * DI + c] = l;
}

// softmax over l per (b, token): writes fp32 Atok (B, Stok, LCP), K-pad zeroed
__global__ void softmax_kernel()
{
    __shared__ float sv[LC];
    __shared__ float red[256];
    int tt = blockIdx.x, b = blockIdx.y, tid = threadIdx.x;
    float mx = -1e30f;
    for (int l = tid; l < LC; l += 256) {
        float v = g_scores[((long long)b * LC + l) * Stok + tt];
        sv[l] = v; mx = fmaxf(mx, v);
    }
    red[tid] = mx; __syncthreads();
    for (int o = 128; o; o >>= 1) { if (tid < o) red[tid] = fmaxf(red[tid], red[tid + o]); __syncthreads(); }
    mx = red[0]; __syncthreads();
    float sum = 0.f;
    for (int l = tid; l < LC; l += 256) { float e = expf(sv[l] - mx); sv[l] = e; sum += e; }
    red[tid] = sum; __syncthreads();
    for (int o = 128; o; o >>= 1) { if (tid < o) red[tid] += red[tid + o]; __syncthreads(); }
    float inv = 1.f / red[0]; __syncthreads();
    long long base = ((long long)b * Stok + tt) * LCP;
    for (int l = tid; l < LC; l += 256) g_atok[base + l] = sv[l] * inv;
    if (tid < LCP - LC) g_atok[base + LC + tid] = 0.f;
}

// ---------------- host launcher ----------------
static inline int ceildiv(int a, int b) { return (a + b - 1) / b; }

extern "C" void kernel_launch(void* const* d_in, const int* in_sizes, int n_in,
                              void* d_out, int out_size)
{
    const float* x        = (const float*)d_in[0];
    const float* W_in_x   = (const float*)d_in[1];
    const float* W_in_z   = (const float*)d_in[2];
    const float* conv_w_f = (const float*)d_in[3];
    const float* conv_b_f = (const float*)d_in[4];
    const float* conv_w_b = (const float*)d_in[5];
    const float* conv_b_b = (const float*)d_in[6];
    const float* W_xp_f   = (const float*)d_in[7];
    const float* b_xp_f   = (const float*)d_in[8];
    const float* W_dt_f   = (const float*)d_in[9];
    const float* b_dt_f   = (const float*)d_in[10];
    const float* A_log_f  = (const float*)d_in[11];
    const float* D_f      = (const float*)d_in[12];
    const float* W_xp_b   = (const float*)d_in[13];
    const float* b_xp_b   = (const float*)d_in[14];
    const float* W_dt_b   = (const float*)d_in[15];
    const float* b_dt_b   = (const float*)d_in[16];
    const float* A_log_b  = (const float*)d_in[17];
    const float* D_b      = (const float*)d_in[18];
    const float* W_pro_to = (const float*)d_in[19];
    const float* b_pro_to = (const float*)d_in[20];
    const float* token_wA = (const float*)d_in[21];
    const float* token_wV = (const float*)d_in[22];
    const float* W_out    = (const float*)d_in[23];
    float* out = (float*)d_out;

    float *xi, *uf, *ub, *dbcf, *dbcb, *def, *deb, *yf, *yb, *ycat, *yy;
    float *mc, *dist, *xpf, *zp, *scores, *atok, *tyb, *T;
    cudaGetSymbolAddress((void**)&xi,   g_xi);
    cudaGetSymbolAddress((void**)&uf,   g_uf);
    cudaGetSymbolAddress((void**)&ub,   g_ub);
    cudaGetSymbolAddress((void**)&dbcf, g_dbcf);
    cudaGetSymbolAddress((void**)&dbcb, g_dbcb);
    cudaGetSymbolAddress((void**)&def,  g_deltaf);
    cudaGetSymbolAddress((void**)&deb,  g_deltab);
    cudaGetSymbolAddress((void**)&yf,   g_yf);
    cudaGetSymbolAddress((void**)&yb,   g_yb);
    cudaGetSymbolAddress((void**)&ycat, g_ycat);
    cudaGetSymbolAddress((void**)&yy,   g_y);
    cudaGetSymbolAddress((void**)&mc,   g_mc);
    cudaGetSymbolAddress((void**)&dist, g_dist);
    cudaGetSymbolAddress((void**)&xpf,  g_xpf);
    cudaGetSymbolAddress((void**)&zp,   g_zp);
    cudaGetSymbolAddress((void**)&scores, g_scores);
    cudaGetSymbolAddress((void**)&atok, g_atok);
    cudaGetSymbolAddress((void**)&tyb,  g_ty);
    cudaGetSymbolAddress((void**)&T,    g_T);

    __nv_bfloat16 *Winxh,*Winxl,*Winzh,*Winzl,*Wxpfh,*Wxpfl,*Wxpbh,*Wxpbl;
    __nv_bfloat16 *Wdtfh,*Wdtfl,*Wdtbh,*Wdtbl,*Wproh,*Wprol,*wAh,*wAl;
    __nv_bfloat16 *wVh,*wVl,*Wouth,*Woutl,*yh2,*yl2;
    cudaGetSymbolAddress((void**)&Winxh, g_Winx_h); cudaGetSymbolAddress((void**)&Winxl, g_Winx_l);
    cudaGetSymbolAddress((void**)&Winzh, g_Winz_h); cudaGetSymbolAddress((void**)&Winzl, g_Winz_l);
    cudaGetSymbolAddress((void**)&Wxpfh, g_Wxpf_h); cudaGetSymbolAddress((void**)&Wxpfl, g_Wxpf_l);
    cudaGetSymbolAddress((void**)&Wxpbh, g_Wxpb_h); cudaGetSymbolAddress((void**)&Wxpbl, g_Wxpb_l);
    cudaGetSymbolAddress((void**)&Wdtfh, g_Wdtf_h); cudaGetSymbolAddress((void**)&Wdtfl, g_Wdtf_l);
    cudaGetSymbolAddress((void**)&Wdtbh, g_Wdtb_h); cudaGetSymbolAddress((void**)&Wdtbl, g_Wdtb_l);
    cudaGetSymbolAddress((void**)&Wproh, g_Wpro_h); cudaGetSymbolAddress((void**)&Wprol, g_Wpro_l);
    cudaGetSymbolAddress((void**)&wAh, g_wA_h);     cudaGetSymbolAddress((void**)&wAl, g_wA_l);
    cudaGetSymbolAddress((void**)&wVh, g_wV_h);     cudaGetSymbolAddress((void**)&wVl, g_wV_l);
    cudaGetSymbolAddress((void**)&Wouth, g_Wout_h); cudaGetSymbolAddress((void**)&Woutl, g_Wout_l);
    cudaGetSymbolAddress((void**)&yh2, g_yh);       cudaGetSymbolAddress((void**)&yl2, g_yl);

    const int ML = Bsz * Lseq;  // 16392
    const int MC = Bsz * LC;    // 8224

    // 0) weight splits (one launch)
    wsplit_kernel<<<WSPLIT_TOT / 256, 256>>>(W_in_x, W_in_z, W_xp_f, W_xp_b,
                                             W_dt_f, W_dt_b, W_pro_to, token_wA,
                                             token_wV, W_out);

    // 1) xi = x @ W_in_x^T
    hgemm3<1><<<dim3(DI / 128, ceildiv(ML, 128)), 256>>>(
        x, Winxh, Winxl, nullptr, nullptr, xi,
        ML, DI, Dmod, Dmod, Dmod, DI, DI, 0, 0, 0, 0);

    // 2) xp pooling; zp = silu(xp @ W_in_z^T)
    pool_kernel<<<dim3(Stok, Bsz), Dmod>>>(x);
    hgemm3<1><<<dim3(DI / 128, 4), 256>>>(
        xpf, Winzh, Winzl, nullptr, nullptr, zp,
        Bsz * Stok, DI, Dmod, Dmod, Dmod, DI, DI, 1, 0, 0, 0);

    // 3) conv + silu (both dirs, one launch)
    conv_silu2_kernel<<<dim3(LC, Bsz, 2), DI>>>(xi, conv_w_f, conv_b_f, conv_w_b, conv_b_b);

    // 4) dbc = u @ W_xp^T + b  (N pad 128, Nout 48)
    hgemm3<1><<<dim3(1, ceildiv(MC, 128)), 256>>>(
        uf, Wxpfh, Wxpfl, b_xp_f, nullptr, dbcf,
        MC, 128, DI, DI, DI, NXP, NXP, 0, 0, 0, 0);
    hgemm3<1><<<dim3(1, ceildiv(MC, 128)), 256>>>(
        ub, Wxpbh, Wxpbl, b_xp_b, nullptr, dbcb,
        MC, 128, DI, DI, DI, NXP, NXP, 0, 0, 0, 0);

    // 5) delta = softplus(dr @ W_dt^T + b_dt)  (K=16 view of dbc, lda=48)
    hgemm3<1><<<dim3(DI / 128, ceildiv(MC, 128)), 256>>>(
        dbcf, Wdtfh, Wdtfl, b_dt_f, nullptr, def,
        MC, DI, DRK, NXP, DRK, DI, DI, 2, 0, 0, 0);
    hgemm3<1><<<dim3(DI / 128, ceildiv(MC, 128)), 256>>>(
        dbcb, Wdtbh, Wdtbl, b_dt_b, nullptr, deb,
        MC, DI, DRK, NXP, DRK, DI, DI, 2, 0, 0, 0);

    // 6) selective scans (both dirs, one launch)
    scan2_kernel<<<dim3(Bsz * DI / 16, 2), 256>>>(A_log_f, D_f, A_log_b, D_b);

    // 7) masks ('last'), both dirs merged
    dist2_kernel<<<dim3(ceildiv(LC, 8), Bsz, 2), 256>>>(LC - 1);
    maskfin2_kernel<<<dim3(Bsz, 2), 512>>>(LC - 1);

    // 8) ycat, y = ycat @ W_pro^T + b
    concat_kernel<<<dim3(LC, Bsz), DI>>>();
    hgemm3<1><<<dim3(DI / 128, ceildiv(MC, 128)), 256>>>(
        ycat, Wproh, Wprol, b_pro_to, nullptr, yy,
        MC, DI, 2 * DI, 2 * DI, 2 * DI, DI, DI, 0, 0, 0, 0);

    // 9) center mask, scale y (in place + split planes)
    dist_kernel<<<dim3(ceildiv(LC, 8), Bsz), 256>>>(yy, dist, (LC + 1) / 2);
    maskfin_kernel<<<Bsz, 512>>>(dist, mc, (LC + 1) / 2);
    scale_y_kernel<<<dim3(LC, Bsz), DI>>>();

    // 10) scores = y @ wA^T (N pad 128, Nout 64), softmax -> Atok fp32 (K-padded)
    hgemm3<1><<<dim3(1, ceildiv(MC, 128)), 256>>>(
        yy, wAh, wAl, nullptr, nullptr, scores,
        MC, 128, DI, DI, DI, Stok, Stok, 0, 0, 0, 0);
    softmax_kernel<<<dim3(Stok, Bsz), 256>>>();

    // 11) Ty = Atok @ y  (TB=0, batched over b, K padded to 1040)
    hgemm3<0><<<dim3(DI / 128, 1, Bsz), 256>>>(
        atok, yh2, yl2, nullptr, nullptr, tyb,
        Stok, DI, LCP, LCP, DI, DI, DI, 0,
        (long long)Stok * LCP, (long long)LC * DI, (long long)Stok * DI);

    // 12) T = (Ty @ wV) * zp  (TB=0, batched, wV shared)
    hgemm3<0><<<dim3(DI / 128, 1, Bsz), 256>>>(
        tyb, wVh, wVl, nullptr, zp, T,
        Stok, DI, DI, DI, DI, DI, DI, 0,
        (long long)Stok * DI, 0, (long long)Stok * DI);

    // 13) out = T @ W_out^T
    hgemm3<1><<<dim3(Dmod / 128, 4), 256>>>(
        T, Wouth, Woutl, nullptr, nullptr, out,
        Bsz * Stok, Dmod, DI, DI, DI, Dmod, Dmod, 0, 0, 0, 0);
}

// round 6
// speedup vs baseline: 1.7695x; 1.3042x over previous
#include <cuda_runtime.h>
#include <cuda_bf16.h>
#include <math.h>
#include <stdint.h>

// ---------------- problem constants ----------------
#define Bsz  8
#define Lseq 2049
#define Dmod 256
#define DI   512
#define DS   16
#define DRK  16
#define LB   1025
#define LC   1028
#define Stok 64
#define NXP  48
#define LCP  1040   // LC padded to 16

#define SZ_U    (Bsz*LC*DI)
#define SZ_DBC  (Bsz*LC*NXP)

// ---------------- fp32 scratch ----------------
__device__ float g_xi[Bsz*Lseq*DI];
__device__ float g_u[2*SZ_U];          // f, b
__device__ float g_dbc[2*SZ_DBC];      // f, b (atomic accum)
__device__ float g_delta[2*SZ_U];
__device__ float g_ysc[2*SZ_U];        // scan outputs f, b
__device__ float g_ycat[Bsz*LC*2*DI];
__device__ float g_y[Bsz*LC*DI];
__device__ float g_mf[Bsz*LC];
__device__ float g_mb[Bsz*LC];
__device__ float g_mc[Bsz*LC];
__device__ float g_dist[Bsz*LC*2];
__device__ float g_xpf[Bsz*Stok*Dmod];
__device__ float g_zpacc[Bsz*Stok*DI];     // atomic accum (pre-silu)
__device__ float g_scores[Bsz*LC*Stok];    // atomic accum
__device__ float g_atok[Bsz*Stok*LCP];
__device__ float g_tyacc[Bsz*Stok*DI];     // atomic accum
__device__ float g_Tacc[Bsz*Stok*DI];      // atomic accum
__device__ float g_T[Bsz*Stok*DI];
// merged biases
__device__ float g_bxp[2*128];
__device__ float g_bdt[2*DI];

// ---------------- bf16 weight planes ----------------
__device__ __nv_bfloat16 g_Winx_h[DI*Dmod],   g_Winx_l[DI*Dmod];
__device__ __nv_bfloat16 g_Winz_h[DI*Dmod],   g_Winz_l[DI*Dmod];
__device__ __nv_bfloat16 g_Wxp_h[2*128*DI],   g_Wxp_l[2*128*DI];   // f, b (row-padded 48->128)
__device__ __nv_bfloat16 g_Wdt_h[2*DI*DRK],   g_Wdt_l[2*DI*DRK];   // f, b
__device__ __nv_bfloat16 g_Wpro_h[DI*2*DI],   g_Wpro_l[DI*2*DI];
__device__ __nv_bfloat16 g_wA_h[128*DI],      g_wA_l[128*DI];
__device__ __nv_bfloat16 g_wV_h[DI*DI],       g_wV_l[DI*DI];
__device__ __nv_bfloat16 g_Wout_h[Dmod*DI],   g_Wout_l[Dmod*DI];
__device__ __nv_bfloat16 g_yh[Bsz*LC*DI+16*DI], g_yl[Bsz*LC*DI+16*DI]; // slack rows stay 0

__device__ __forceinline__ void splitv(float v, __nv_bfloat16& h, __nv_bfloat16& l) {
    h = __float2bfloat16(v);
    l = __float2bfloat16(v - __bfloat162float(h));
}

// ---------------- fused weight split + bias concat (one launch) ----------------
__global__ void wsplit_kernel(const float* __restrict__ Winx, const float* __restrict__ Winz,
                              const float* __restrict__ Wxpf, const float* __restrict__ Wxpb,
                              const float* __restrict__ Wdtf, const float* __restrict__ Wdtb,
                              const float* __restrict__ Wpro, const float* __restrict__ wA,
                              const float* __restrict__ wV,   const float* __restrict__ Wout,
                              const float* __restrict__ bxpf, const float* __restrict__ bxpb,
                              const float* __restrict__ bdtf, const float* __restrict__ bdtb)
{
    int i = blockIdx.x * 256 + threadIdx.x;
    __nv_bfloat16 h, l;
    if (i < 131072) { splitv(Winx[i], h, l); g_Winx_h[i] = h; g_Winx_l[i] = l; return; }
    i -= 131072;
    if (i < 131072) { splitv(Winz[i], h, l); g_Winz_h[i] = h; g_Winz_l[i] = l; return; }
    i -= 131072;
    if (i < 131072) {   // Wxp merged: dir*65536 + r*512 + c, rows >= 48 zero
        int dir = i >> 16, j = i & 65535;
        int r = j >> 9, c = j & 511;
        const float* W = dir ? Wxpb : Wxpf;
        splitv(r < NXP ? W[r * DI + c] : 0.f, h, l);
        g_Wxp_h[i] = h; g_Wxp_l[i] = l; return; }
    i -= 131072;
    if (i < 16384) {    // Wdt merged
        int dir = i >> 13, j = i & 8191;
        const float* W = dir ? Wdtb : Wdtf;
        splitv(W[j], h, l); g_Wdt_h[i] = h; g_Wdt_l[i] = l; return; }
    i -= 16384;
    if (i < 524288) { splitv(Wpro[i], h, l); g_Wpro_h[i] = h; g_Wpro_l[i] = l; return; }
    i -= 524288;
    if (i < 65536) { int r = i >> 9, c = i & 511;
        splitv(r < Stok ? wA[r * DI + c] : 0.f, h, l);
        g_wA_h[i] = h; g_wA_l[i] = l; return; }
    i -= 65536;
    if (i < 262144) { splitv(wV[i], h, l); g_wV_h[i] = h; g_wV_l[i] = l; return; }
    i -= 262144;
    if (i < 131072) { splitv(Wout[i], h, l); g_Wout_h[i] = h; g_Wout_l[i] = l; return; }
    i -= 131072;
    if (i < 256) {      // bxp merged, pad zero
        int dir = i >> 7, r = i & 127;
        const float* bsrc = dir ? bxpb : bxpf;
        g_bxp[i] = (r < NXP) ? bsrc[r] : 0.f; return; }
    i -= 256;
    if (i < 1024) {     // bdt merged
        int dir = i >> 9, r = i & 511;
        g_bdt[i] = dir ? bdtb[r] : bdtf[r]; }
}
#define WSPLIT_TOT 1393920

// ---------------- zero accum buffers + d_out (one launch) ----------------
__global__ void zero_acc_kernel(float* __restrict__ dout)
{
    long long i = (long long)blockIdx.x * 256 + threadIdx.x;
    if (i < Bsz*Stok*DI) { g_zpacc[i] = 0.f; return; }  i -= Bsz*Stok*DI;
    if (i < 2*SZ_DBC)    { g_dbc[i] = 0.f; return; }    i -= 2*SZ_DBC;
    if (i < Bsz*LC*Stok) { g_scores[i] = 0.f; return; } i -= Bsz*LC*Stok;
    if (i < Bsz*Stok*DI) { g_tyacc[i] = 0.f; return; }  i -= Bsz*Stok*DI;
    if (i < Bsz*Stok*DI) { g_Tacc[i] = 0.f; return; }   i -= Bsz*Stok*DI;
    if (i < Bsz*Stok*Dmod) dout[i] = 0.f;
}
#define ZERO_TOT (Bsz*Stok*DI + 2*SZ_DBC + Bsz*LC*Stok + Bsz*Stok*DI + Bsz*Stok*DI + Bsz*Stok*Dmod)

// =====================================================================
// hgemm4: C = A(fp32, M x K) * op(B pre-split bf16 planes), 3-split MMA.
// TB=1: B planes (N,K) row-major; TB=0: (K,N) row-major.
// N % 128 == 0 (buffer domain), writes guarded by Nout; (K/KS) % 16 == 0.
// gridDim.z = nDir * KS; dir = z / KS (buffer strides), ks = z % KS.
// KS > 1: atomicAdd epilogue (act must be 0, emul null, bias on ks==0).
// =====================================================================
#define SAS 24

__device__ __forceinline__ uint32_t s2u(const void* p) {
    return (uint32_t)__cvta_generic_to_shared(p);
}
__device__ __forceinline__ void ldsm4(uint32_t r[4], uint32_t addr) {
    asm volatile("ldmatrix.sync.aligned.m8n8.x4.shared.b16 {%0,%1,%2,%3}, [%4];"
                 : "=r"(r[0]), "=r"(r[1]), "=r"(r[2]), "=r"(r[3]) : "r"(addr));
}
__device__ __forceinline__ void mma16816(float c[4], const uint32_t a[4],
                                         uint32_t b0, uint32_t b1) {
    asm volatile(
        "mma.sync.aligned.m16n8k16.row.col.f32.bf16.bf16.f32 "
        "{%0,%1,%2,%3},{%4,%5,%6,%7},{%8,%9},{%0,%1,%2,%3};"
        : "+f"(c[0]), "+f"(c[1]), "+f"(c[2]), "+f"(c[3])
        : "r"(a[0]), "r"(a[1]), "r"(a[2]), "r"(a[3]), "r"(b0), "r"(b1));
}

template<int TB>
__global__ __launch_bounds__(256, 2)
void hgemm4(const float* __restrict__ A,
            const __nv_bfloat16* __restrict__ Bh, const __nv_bfloat16* __restrict__ Bl,
            const float* __restrict__ bias, const float* __restrict__ emul,
            float* __restrict__ C,
            int M, int N, int K, int lda, int ldb, int ldc, int Nout, int act, int KS,
            long long sA, long long sB, long long sC, long long sBias)
{
    __shared__ __align__(16) __nv_bfloat16 As_hi[128][SAS];
    __shared__ __align__(16) __nv_bfloat16 As_lo[128][SAS];
    __shared__ __align__(16) __nv_bfloat16 Bs_hi[128][SAS];
    __shared__ __align__(16) __nv_bfloat16 Bs_lo[128][SAS];

    int bz  = blockIdx.z;
    int dir = bz / KS;
    int ks  = bz % KS;
    A  += dir * sA;
    Bh += dir * sB; Bl += dir * sB;
    if (bias) bias += dir * sBias;
    int kchunk = K / KS;
    int kb = ks * kchunk, ke = kb + kchunk;

    int tid  = threadIdx.x;
    int lane = tid & 31;
    int wid  = tid >> 5;
    int wm0  = (wid >> 2) * 64;
    int wn0  = (wid & 3) * 32;
    int row0 = blockIdx.y * 128;
    int col0 = blockIdx.x * 128;

    int lr = lane & 15;
    int lc = (lane >> 4) * 8;

    int ar = tid >> 1;
    int ac = (tid & 1) * 8;
    int gm = row0 + ar;
    bool mok = gm < M;
    const float* Ap = A + (long long)gm * lda + ac;

    const __nv_bfloat16 *Bph = nullptr, *Bpl = nullptr;
    int bkk = 0, bnc = 0;
    if (TB == 1) {
        Bph = Bh + (long long)(col0 + ar) * ldb + ac;
        Bpl = Bl + (long long)(col0 + ar) * ldb + ac;
    } else {
        bkk = tid >> 4;
        bnc = (tid & 15) * 8;
        Bph = Bh + col0 + bnc;
        Bpl = Bl + col0 + bnc;
    }

    float4 ra0 = make_float4(0,0,0,0), ra1 = make_float4(0,0,0,0);
    uint4 rbh, rbl;

    if (mok) { ra0 = *(const float4*)(Ap + kb); ra1 = *(const float4*)(Ap + kb + 4); }
    if (TB == 1) {
        rbh = *(const uint4*)(Bph + kb); rbl = *(const uint4*)(Bpl + kb);
    } else {
        rbh = *(const uint4*)(Bph + (long long)(kb + bkk) * ldb);
        rbl = *(const uint4*)(Bpl + (long long)(kb + bkk) * ldb);
    }

    float acc[4][4][4];
    #pragma unroll
    for (int i = 0; i < 4; i++)
        #pragma unroll
        for (int j = 0; j < 4; j++)
            #pragma unroll
            for (int q = 0; q < 4; q++) acc[i][j][q] = 0.f;

    for (int k0 = kb; k0 < ke; k0 += 16) {
        {
            float av[8] = {ra0.x, ra0.y, ra0.z, ra0.w, ra1.x, ra1.y, ra1.z, ra1.w};
            __nv_bfloat16 hh[8], ll[8];
            #pragma unroll
            for (int j = 0; j < 8; j++) splitv(av[j], hh[j], ll[j]);
            *(uint4*)&As_hi[ar][ac] = *(uint4*)hh;
            *(uint4*)&As_lo[ar][ac] = *(uint4*)ll;
        }
        if (TB == 1) {
            *(uint4*)&Bs_hi[ar][ac] = rbh;
            *(uint4*)&Bs_lo[ar][ac] = rbl;
        } else {
            __nv_bfloat16 th[8], tl[8];
            *(uint4*)th = rbh; *(uint4*)tl = rbl;
            #pragma unroll
            for (int j = 0; j < 8; j++) {
                Bs_hi[bnc + j][bkk] = th[j];
                Bs_lo[bnc + j][bkk] = tl[j];
            }
        }
        __syncthreads();

        if (k0 + 16 < ke) {
            if (mok) {
                ra0 = *(const float4*)(Ap + k0 + 16);
                ra1 = *(const float4*)(Ap + k0 + 20);
            }
            if (TB == 1) {
                rbh = *(const uint4*)(Bph + k0 + 16);
                rbl = *(const uint4*)(Bpl + k0 + 16);
            } else {
                rbh = *(const uint4*)(Bph + (long long)(k0 + 16 + bkk) * ldb);
                rbl = *(const uint4*)(Bpl + (long long)(k0 + 16 + bkk) * ldb);
            }
        }

        uint32_t bhf[2][4], blf[2][4];
        #pragma unroll
        for (int ng = 0; ng < 2; ng++) {
            ldsm4(bhf[ng], s2u(&Bs_hi[wn0 + ng * 16 + lr][lc]));
            ldsm4(blf[ng], s2u(&Bs_lo[wn0 + ng * 16 + lr][lc]));
        }
        #pragma unroll
        for (int mt = 0; mt < 4; mt++) {
            uint32_t a_h[4], a_l[4];
            ldsm4(a_h, s2u(&As_hi[wm0 + mt * 16 + lr][lc]));
            ldsm4(a_l, s2u(&As_lo[wm0 + mt * 16 + lr][lc]));
            #pragma unroll
            for (int nt = 0; nt < 4; nt++) {
                int ng = nt >> 1, sl = nt & 1;
                mma16816(acc[mt][nt], a_h, bhf[ng][sl], bhf[ng][sl + 2]);
                mma16816(acc[mt][nt], a_h, blf[ng][sl], blf[ng][sl + 2]);
                mma16816(acc[mt][nt], a_l, bhf[ng][sl], bhf[ng][sl + 2]);
            }
        }
        __syncthreads();
    }

    // ---- epilogue ----
    int g = lane >> 2, t4 = lane & 3;
    #pragma unroll
    for (int mt = 0; mt < 4; mt++) {
        #pragma unroll
        for (int nt = 0; nt < 4; nt++) {
            int cb = col0 + wn0 + nt * 8 + 2 * t4;
            if (cb >= Nout) continue;
            float b0 = 0.f, b1 = 0.f;
            if (bias && (KS == 1 || ks == 0)) { b0 = bias[cb]; b1 = bias[cb + 1]; }
            #pragma unroll
            for (int hrow = 0; hrow < 2; hrow++) {
                int m = row0 + wm0 + mt * 16 + g + hrow * 8;
                if (m >= M) continue;
                float v0 = acc[mt][nt][hrow * 2 + 0] + b0;
                float v1 = acc[mt][nt][hrow * 2 + 1] + b1;
                long long co = dir * sC + (long long)m * ldc + cb;
                if (KS > 1) {
                    atomicAdd(C + co, v0);
                    atomicAdd(C + co + 1, v1);
                } else {
                    if (act == 1) {
                        v0 = v0 / (1.f + expf(-v0));
                        v1 = v1 / (1.f + expf(-v1));
                    } else if (act == 2) {
                        v0 = (v0 > 20.f) ? v0 : log1pf(expf(v0));
                        v1 = (v1 > 20.f) ? v1 : log1pf(expf(v1));
                    }
                    if (emul) { v0 *= emul[co]; v1 *= emul[co + 1]; }
                    *(float2*)(C + co) = make_float2(v0, v1);
                }
            }
        }
    }
}

// ---------------- pooling of x (P @ x) -> fp32 ----------------
__global__ void pool_kernel(const float* __restrict__ x)
{
    int s = blockIdx.x, b = blockIdx.y, d = threadIdx.x;
    int s0 = (s * Lseq) / Stok;
    int e  = ((s + 1) * Lseq + Stok - 1) / Stok;
    float acc = 0.f;
    for (int l = s0; l < e; l++) acc += x[((long long)b * Lseq + l) * Dmod + d];
    g_xpf[((long long)b * Stok + s) * Dmod + d] = acc / (float)(e - s0);
}

// ---------------- depthwise conv + SiLU, both directions ----------------
__global__ void conv_silu2_kernel(const float* __restrict__ xi,
                                  const float* __restrict__ wf, const float* __restrict__ bf,
                                  const float* __restrict__ wb, const float* __restrict__ bb)
{
    int t = blockIdx.x;
    int b = blockIdx.y;
    int back = blockIdx.z;
    int c = threadIdx.x;
    const float* w  = back ? wb : wf;
    float acc       = back ? bb[c] : bf[c];
    float* out      = g_u + (long long)back * SZ_U;
    #pragma unroll
    for (int k = 0; k < 4; k++) {
        int i = t + k - 3;
        if (i >= 0 && i < LB) {
            int l = back ? (Lseq - 1 - i) : i;
            acc = fmaf(w[c * 4 + k], xi[((long long)b * Lseq + l) * DI + c], acc);
        }
    }
    out[((long long)b * LC + t) * DI + c] = acc / (1.f + expf(-acc));
}

// ---------------- selective scans, both directions ----------------
__global__ __launch_bounds__(256)
void scan2_kernel(const float* __restrict__ A_log_f, const float* __restrict__ D_f,
                  const float* __restrict__ A_log_b, const float* __restrict__ D_b)
{
    int back = blockIdx.y;
    const float* u     = g_u     + (long long)back * SZ_U;
    const float* delta = g_delta + (long long)back * SZ_U;
    const float* dbc   = g_dbc   + (long long)back * SZ_DBC;
    const float* A_log = back ? A_log_b : A_log_f;
    const float* Dp    = back ? D_b : D_f;
    float* y           = g_ysc   + (long long)back * SZ_U;

    int gid = blockIdx.x * 16 + (threadIdx.x >> 4);
    int s = threadIdx.x & 15;
    int b = gid >> 9;
    int d = gid & 511;
    float Av = -expf(A_log[d * 16 + s]);
    float Dd = Dp[d];
    float h = 0.f;
    const float* db = dbc + (long long)b * LC * NXP;
    const float* dl = delta + ((long long)b * LC) * DI + d;
    const float* uu = u     + ((long long)b * LC) * DI + d;
    float*       yy = y     + ((long long)b * LC) * DI + d;
    for (int t = 0; t < LC; t++) {
        float de = __ldg(dl + (long long)t * DI);
        float uv = __ldg(uu + (long long)t * DI);
        float Bv = __ldg(db + t * NXP + DRK + s);
        float Cv = __ldg(db + t * NXP + DRK + DS + s);
        float dA = __expf(de * Av);
        h = fmaf(dA, h, de * uv * Bv);
        float v = h * Cv;
        v += __shfl_xor_sync(0xffffffffu, v, 8);
        v += __shfl_xor_sync(0xffffffffu, v, 4);
        v += __shfl_xor_sync(0xffffffffu, v, 2);
        v += __shfl_xor_sync(0xffffffffu, v, 1);
        if (s == 0) yy[(long long)t * DI] = fmaf(Dd, uv, v);
    }
}

// ---------------- gaussian masks ----------------
__global__ void dist2_kernel(int ref)
{
    int back = blockIdx.z;
    const float* y = g_ysc + (long long)back * SZ_U;
    float* dist = g_dist + back * (Bsz * LC);
    int b = blockIdx.y;
    int t = blockIdx.x * 8 + (threadIdx.x >> 5);
    int lane = threadIdx.x & 31;
    if (t >= LC) return;
    const float* yt = y + ((long long)b * LC + t) * DI;
    const float* yr = y + ((long long)b * LC + ref) * DI;
    float acc = 0.f;
    for (int d = lane; d < DI; d += 32) {
        float df = yt[d] - yr[d];
        acc = fmaf(df, df, acc);
    }
    #pragma unroll
    for (int o = 16; o; o >>= 1) acc += __shfl_xor_sync(0xffffffffu, acc, o);
    if (lane == 0) dist[b * LC + t] = sqrtf(fmaxf(acc, 1e-12f));
}

__global__ void dist_kernel(const float* __restrict__ y, float* __restrict__ dist, int ref)
{
    int b = blockIdx.y;
    int t = blockIdx.x * 8 + (threadIdx.x >> 5);
    int lane = threadIdx.x & 31;
    if (t >= LC) return;
    const float* yt = y + ((long long)b * LC + t) * DI;
    const float* yr = y + ((long long)b * LC + ref) * DI;
    float acc = 0.f;
    for (int d = lane; d < DI; d += 32) {
        float df = yt[d] - yr[d];
        acc = fmaf(df, df, acc);
    }
    #pragma unroll
    for (int o = 16; o; o >>= 1) acc += __shfl_xor_sync(0xffffffffu, acc, o);
    if (lane == 0) dist[b * LC + t] = sqrtf(fmaxf(acc, 1e-12f));
}

__device__ __forceinline__ void maskfin_body(const float* dist, float* m, int ref,
                                             float* red, int tid)
{
    float s = 0.f;
    for (int t = tid; t < LC; t += 512) s += dist[t];
    red[tid] = s; __syncthreads();
    for (int o = 256; o; o >>= 1) { if (tid < o) red[tid] += red[tid + o]; __syncthreads(); }
    float sigv = red[0] / (float)LC;
    __syncthreads();
    float si = ((float)ref * (float)(ref + 1) * 0.5f +
                (float)(LC - 1 - ref) * (float)(LC - ref) * 0.5f) / (float)LC;
    float c_i = 0.5f / (si * si);
    float c_v = 0.5f / (sigv * sigv);
    float nrm = 0.f;
    for (int t = tid; t < LC; t += 512) {
        float dt = (float)(t - ref);
        float dv = dist[t];
        float p = expf(-dt * dt * c_i - dv * dv * c_v);
        m[t] = p;
        nrm = fmaf(p, p, nrm);
    }
    red[tid] = nrm; __syncthreads();
    for (int o = 256; o; o >>= 1) { if (tid < o) red[tid] += red[tid + o]; __syncthreads(); }
    float inv = 1.f / fmaxf(sqrtf(red[0]), 1e-12f);
    __syncthreads();
    for (int t = tid; t < LC; t += 512) m[t] *= inv;
}

__global__ void maskfin2_kernel(int ref)
{
    __shared__ float red[512];
    int back = blockIdx.y;
    int b = blockIdx.x;
    const float* dist = g_dist + back * (Bsz * LC) + b * LC;
    float* m = (back ? g_mb : g_mf) + b * LC;
    maskfin_body(dist, m, ref, red, threadIdx.x);
}

__global__ void maskfin_kernel(const float* __restrict__ dist, float* __restrict__ m, int ref)
{
    __shared__ float red[512];
    int b = blockIdx.x;
    maskfin_body(dist + b * LC, m + b * LC, ref, red, threadIdx.x);
}

// ycat = [ y_f * m_f , y_b * reverse(m_b) ]
__global__ void concat_kernel()
{
    int t = blockIdx.x, b = blockIdx.y, c = threadIdx.x;
    long long r = (long long)b * LC + t;
    g_ycat[r * (2 * DI) + c]      = g_ysc[r * DI + c] * g_mf[b * LC + t];
    g_ycat[r * (2 * DI) + DI + c] = g_ysc[SZ_U + r * DI + c] * g_mb[b * LC + (LC - 1 - t)];
}

// y *= mc (in place) + bf16 split planes
__global__ void scale_y_kernel()
{
    int t = blockIdx.x, b = blockIdx.y, c = threadIdx.x;
    long long r = (long long)b * LC + t;
    float v = g_y[r * DI + c] * g_mc[b * LC + t];
    g_y[r * DI + c] = v;
    __nv_bfloat16 h, l; splitv(v, h, l);
    g_yh[r * DI + c] = h; g_yl[r * DI + c] = l;
}

// softmax over l per (b, token): fp32 Atok (B, Stok, LCP), pad zeroed
__global__ void softmax_kernel()
{
    __shared__ float sv[LC];
    __shared__ float red[256];
    int tt = blockIdx.x, b = blockIdx.y, tid = threadIdx.x;
    float mx = -1e30f;
    for (int l = tid; l < LC; l += 256) {
        float v = g_scores[((long long)b * LC + l) * Stok + tt];
        sv[l] = v; mx = fmaxf(mx, v);
    }
    red[tid] = mx; __syncthreads();
    for (int o = 128; o; o >>= 1) { if (tid < o) red[tid] = fmaxf(red[tid], red[tid + o]); __syncthreads(); }
    mx = red[0]; __syncthreads();
    float sum = 0.f;
    for (int l = tid; l < LC; l += 256) { float e = expf(sv[l] - mx); sv[l] = e; sum += e; }
    red[tid] = sum; __syncthreads();
    for (int o = 128; o; o >>= 1) { if (tid < o) red[tid] += red[tid + o]; __syncthreads(); }
    float inv = 1.f / red[0]; __syncthreads();
    long long base = ((long long)b * Stok + tt) * LCP;
    for (int l = tid; l < LC; l += 256) g_atok[base + l] = sv[l] * inv;
    if (tid < LCP - LC) g_atok[base + LC + tid] = 0.f;
}

// T = Tacc * silu(zpacc)
__global__ void tfinish_kernel()
{
    int i = blockIdx.x * 256 + threadIdx.x;
    if (i >= Bsz * Stok * DI) return;
    float z = g_zpacc[i];
    float s = z / (1.f + expf(-z));
    g_T[i] = g_Tacc[i] * s;
}

// ---------------- host launcher ----------------
static inline int ceildiv(int a, int b) { return (a + b - 1) / b; }

extern "C" void kernel_launch(void* const* d_in, const int* in_sizes, int n_in,
                              void* d_out, int out_size)
{
    const float* x        = (const float*)d_in[0];
    const float* W_in_x   = (const float*)d_in[1];
    const float* W_in_z   = (const float*)d_in[2];
    const float* conv_w_f = (const float*)d_in[3];
    const float* conv_b_f = (const float*)d_in[4];
    const float* conv_w_b = (const float*)d_in[5];
    const float* conv_b_b = (const float*)d_in[6];
    const float* W_xp_f   = (const float*)d_in[7];
    const float* b_xp_f   = (const float*)d_in[8];
    const float* W_dt_f   = (const float*)d_in[9];
    const float* b_dt_f   = (const float*)d_in[10];
    const float* A_log_f  = (const float*)d_in[11];
    const float* D_f      = (const float*)d_in[12];
    const float* W_xp_b   = (const float*)d_in[13];
    const float* b_xp_b   = (const float*)d_in[14];
    const float* W_dt_b   = (const float*)d_in[15];
    const float* b_dt_b   = (const float*)d_in[16];
    const float* A_log_b  = (const float*)d_in[17];
    const float* D_b      = (const float*)d_in[18];
    const float* W_pro_to = (const float*)d_in[19];
    const float* b_pro_to = (const float*)d_in[20];
    const float* token_wA = (const float*)d_in[21];
    const float* token_wV = (const float*)d_in[22];
    const float* W_out    = (const float*)d_in[23];
    float* out = (float*)d_out;

    float *xi, *u, *dbc, *delta, *ycat, *yy, *mc, *dist, *xpf, *zpacc;
    float *scores, *atok, *tyacc, *Tacc, *Tbuf, *bxp, *bdt;
    cudaGetSymbolAddress((void**)&xi,    g_xi);
    cudaGetSymbolAddress((void**)&u,     g_u);
    cudaGetSymbolAddress((void**)&dbc,   g_dbc);
    cudaGetSymbolAddress((void**)&delta, g_delta);
    cudaGetSymbolAddress((void**)&ycat,  g_ycat);
    cudaGetSymbolAddress((void**)&yy,    g_y);
    cudaGetSymbolAddress((void**)&mc,    g_mc);
    cudaGetSymbolAddress((void**)&dist,  g_dist);
    cudaGetSymbolAddress((void**)&xpf,   g_xpf);
    cudaGetSymbolAddress((void**)&zpacc, g_zpacc);
    cudaGetSymbolAddress((void**)&scores, g_scores);
    cudaGetSymbolAddress((void**)&atok,  g_atok);
    cudaGetSymbolAddress((void**)&tyacc, g_tyacc);
    cudaGetSymbolAddress((void**)&Tacc,  g_Tacc);
    cudaGetSymbolAddress((void**)&Tbuf,  g_T);
    cudaGetSymbolAddress((void**)&bxp,   g_bxp);
    cudaGetSymbolAddress((void**)&bdt,   g_bdt);

    __nv_bfloat16 *Winxh,*Winxl,*Winzh,*Winzl,*Wxph,*Wxpl,*Wdth,*Wdtl;
    __nv_bfloat16 *Wproh,*Wprol,*wAh,*wAl,*wVh,*wVl,*Wouth,*Woutl,*yh2,*yl2;
    cudaGetSymbolAddress((void**)&Winxh, g_Winx_h); cudaGetSymbolAddress((void**)&Winxl, g_Winx_l);
    cudaGetSymbolAddress((void**)&Winzh, g_Winz_h); cudaGetSymbolAddress((void**)&Winzl, g_Winz_l);
    cudaGetSymbolAddress((void**)&Wxph, g_Wxp_h);   cudaGetSymbolAddress((void**)&Wxpl, g_Wxp_l);
    cudaGetSymbolAddress((void**)&Wdth, g_Wdt_h);   cudaGetSymbolAddress((void**)&Wdtl, g_Wdt_l);
    cudaGetSymbolAddress((void**)&Wproh, g_Wpro_h); cudaGetSymbolAddress((void**)&Wprol, g_Wpro_l);
    cudaGetSymbolAddress((void**)&wAh, g_wA_h);     cudaGetSymbolAddress((void**)&wAl, g_wA_l);
    cudaGetSymbolAddress((void**)&wVh, g_wV_h);     cudaGetSymbolAddress((void**)&wVl, g_wV_l);
    cudaGetSymbolAddress((void**)&Wouth, g_Wout_h); cudaGetSymbolAddress((void**)&Woutl, g_Wout_l);
    cudaGetSymbolAddress((void**)&yh2, g_yh);       cudaGetSymbolAddress((void**)&yl2, g_yl);

    const int ML = Bsz * Lseq;  // 16392
    const int MC = Bsz * LC;    // 8224

    // 0) zero accum buffers + weight splits
    zero_acc_kernel<<<ceildiv(ZERO_TOT, 256), 256>>>(out);
    wsplit_kernel<<<ceildiv(WSPLIT_TOT, 256), 256>>>(
        W_in_x, W_in_z, W_xp_f, W_xp_b, W_dt_f, W_dt_b, W_pro_to,
        token_wA, token_wV, W_out, b_xp_f, b_xp_b, b_dt_f, b_dt_b);

    // 1) xi = x @ W_in_x^T
    hgemm4<1><<<dim3(DI / 128, ceildiv(ML, 128)), 256>>>(
        x, Winxh, Winxl, nullptr, nullptr, xi,
        ML, DI, Dmod, Dmod, Dmod, DI, DI, 0, 1, 0, 0, 0, 0);

    // 2) pooling; zpacc = xp @ W_in_z^T (split-K4; silu deferred to tfinish)
    pool_kernel<<<dim3(Stok, Bsz), Dmod>>>(x);
    hgemm4<1><<<dim3(DI / 128, 4, 4), 256>>>(
        xpf, Winzh, Winzl, nullptr, nullptr, zpacc,
        Bsz * Stok, DI, Dmod, Dmod, Dmod, DI, DI, 0, 4, 0, 0, 0, 0);

    // 3) conv + silu (both dirs)
    conv_silu2_kernel<<<dim3(LC, Bsz, 2), DI>>>(xi, conv_w_f, conv_b_f, conv_w_b, conv_b_b);

    // 4) dbc = u @ W_xp^T + b  (merged dirs, split-K2, atomic)
    hgemm4<1><<<dim3(1, ceildiv(MC, 128), 4), 256>>>(
        u, Wxph, Wxpl, bxp, nullptr, dbc,
        MC, 128, DI, DI, DI, NXP, NXP, 0, 2,
        (long long)SZ_U, (long long)128 * DI, (long long)SZ_DBC, 128);

    // 5) delta = softplus(dr @ W_dt^T + b_dt)  (merged dirs, K=16)
    hgemm4<1><<<dim3(DI / 128, ceildiv(MC, 128), 2), 256>>>(
        dbc, Wdth, Wdtl, bdt, nullptr, delta,
        MC, DI, DRK, NXP, DRK, DI, DI, 2, 1,
        (long long)SZ_DBC, (long long)DI * DRK, (long long)SZ_U, DI);

    // 6) selective scans (both dirs)
    scan2_kernel<<<dim3(Bsz * DI / 16, 2), 256>>>(A_log_f, D_f, A_log_b, D_b);

    // 7) masks ('last'), both dirs
    dist2_kernel<<<dim3(ceildiv(LC, 8), Bsz, 2), 256>>>(LC - 1);
    maskfin2_kernel<<<dim3(Bsz, 2), 512>>>(LC - 1);

    // 8) ycat; y = ycat @ W_pro^T + b
    concat_kernel<<<dim3(LC, Bsz), DI>>>();
    hgemm4<1><<<dim3(DI / 128, ceildiv(MC, 128)), 256>>>(
        ycat, Wproh, Wprol, b_pro_to, nullptr, yy,
        MC, DI, 2 * DI, 2 * DI, 2 * DI, DI, DI, 0, 1, 0, 0, 0, 0);

    // 9) center mask; scale y + split planes
    dist_kernel<<<dim3(ceildiv(LC, 8), Bsz), 256>>>(yy, dist, (LC + 1) / 2);
    maskfin_kernel<<<Bsz, 512>>>(dist, mc, (LC + 1) / 2);
    scale_y_kernel<<<dim3(LC, Bsz), DI>>>();

    // 10) scores = y @ wA^T (split-K2, atomic); softmax -> Atok
    hgemm4<1><<<dim3(1, ceildiv(MC, 128), 2), 256>>>(
        yy, wAh, wAl, nullptr, nullptr, scores,
        MC, 128, DI, DI, DI, Stok, Stok, 0, 2, 0, 0, 0, 0);
    softmax_kernel<<<dim3(Stok, Bsz), 256>>>();

    // 11) Ty = Atok @ y  (TB=0, dir=b, split-K5, atomic)
    hgemm4<0><<<dim3(DI / 128, 1, Bsz * 5), 256>>>(
        atok, yh2, yl2, nullptr, nullptr, tyacc,
        Stok, DI, LCP, LCP, DI, DI, DI, 0, 5,
        (long long)Stok * LCP, (long long)LC * DI, (long long)Stok * DI, 0);

    // 12) Tacc = Ty @ wV  (TB=0, dir=b, split-K4, atomic); T = Tacc*silu(zpacc)
    hgemm4<0><<<dim3(DI / 128, 1, Bsz * 4), 256>>>(
        tyacc, wVh, wVl, nullptr, nullptr, Tacc,
        Stok, DI, DI, DI, DI, DI, DI, 0, 4,
        (long long)Stok * DI, 0, (long long)Stok * DI, 0);
    tfinish_kernel<<<ceildiv(Bsz * Stok * DI, 256), 256>>>();

    // 13) out = T @ W_out^T  (split-K4, atomic into zeroed d_out)
    hgemm4<1><<<dim3(Dmod / 128, 4, 4), 256>>>(
        Tbuf, Wouth, Woutl, nullptr, nullptr, out,
        Bsz * Stok, Dmod, DI, DI, DI, Dmod, Dmod, 0, 4, 0, 0, 0, 0);
}